// round 14
// baseline (speedup 1.0000x reference)
#include <cuda_runtime.h>
#include <cstdint>

#define NIMG 256
#define IMGS_PER_BLK 8

// Layers: cin {3,344,352,686,679,1246} cout {344,352,686,679,1246,973}
// conv H=W {32,32,16,16,8,8}; pool fused into conv1/3/5 epilogues (shfl OR).
// WINP (storage stride) {1,12,12,24,24,40}, WOUTP stride {12,12,24,24,40,32}
// grid.y (computed cout groups) {12,11,24,22,40,31}; pooled pad words
// (l1:11, l3:22/23, l5:31) zeroed by the wi==0 writer lanes.
// Packed weight words/layer: cum {0,3456,44928,127872,293760,570240}, tot 938880

__device__ uint32_t g_bufA[(size_t)NIMG * 32 * 32 * 12];
__device__ uint32_t g_bufB[(size_t)NIMG * 32 * 32 * 12];
__device__ uint32_t g_wpk[938880];
__device__ int      g_wpw[41472];        // per (layer, wi, tap, cl): popc of weight row
__device__ float2   g_th[4608];          // per-channel (scale, beta - mean*scale)
__device__ uint32_t g_fcpk[10 * 16 * 32];

// Force IMAD (fma pipe) for accumulation; k is a runtime-opaque 1 or 2.
__device__ __forceinline__ void madacc(int& d, int p, int k) {
    asm("mad.lo.s32 %0, %1, %2, %0;" : "+r"(d) : "r"(p), "r"(k));
}

// ---------------------------------------------------------------------------
// Merged pack: x activations + all conv weights (warp per (layer,wi,cl,q),
// each thread reads 9 contiguous floats -> 9 ballots).
__global__ void pack_xw_kernel(const float* __restrict__ x,
                               const float* __restrict__ w0, const float* __restrict__ w1,
                               const float* __restrict__ w2, const float* __restrict__ w3,
                               const float* __restrict__ w4, const float* __restrict__ w5,
                               uint32_t* __restrict__ dstx, uint32_t* __restrict__ dstw)
{
    int idx = blockIdx.x * blockDim.x + threadIdx.x;
    if (idx < NIMG * 1024) {
        int n = idx >> 10, pix = idx & 1023;
        const float* xb = x + (size_t)n * 3 * 1024 + pix;
        uint32_t w = 0;
        if (xb[0]    > 0.f) w |= 1u;
        if (xb[1024] > 0.f) w |= 2u;
        if (xb[2048] > 0.f) w |= 4u;
        dstx[idx] = w;
        return;
    }
    const int cumw[7] = {0, 384, 4992, 14208, 32640, 63360, 104320};
    const int woff[6] = {0, 3456, 44928, 127872, 293760, 570240};
    const int cin[6]  = {3, 344, 352, 686, 679, 1246};
    const int cout[6] = {344, 352, 686, 679, 1246, 973};
    const int winp[6] = {1, 12, 12, 24, 24, 40};

    int wn = (idx >> 5) - 8192;
    int lane = idx & 31;
    if (wn >= 104320) return;

    int l = 0;
#pragma unroll
    for (int i = 1; i < 6; ++i) if (wn >= cumw[i]) l = i;

    const float* wsrc = (l == 0) ? w0 : (l == 1) ? w1 : (l == 2) ? w2
                       : (l == 3) ? w3 : (l == 4) ? w4 : w5;
    const int Ci = cin[l], Co = cout[l], WINP = winp[l];

    int widx = wn - cumw[l];
    int q  = widx % WINP;  widx /= WINP;
    int cl = widx & 31;
    int wi = widx >> 5;
    int co = wi * 32 + cl;
    int ci = q * 32 + lane;

    const bool valid = (co < Co && ci < Ci);
    const float* src = valid ? (wsrc + ((size_t)co * Ci + ci) * 9) : wsrc;
    uint32_t* dbase = dstw + woff[l] + ((size_t)wi * 9 * 32 + cl) * WINP + q;
#pragma unroll
    for (int tap = 0; tap < 9; ++tap) {
        float v = valid ? src[tap] : 0.f;
        uint32_t bits = __ballot_sync(0xFFFFFFFFu, valid && v > 0.f);
        if (lane == 0) dbase[(size_t)tap * 32 * WINP] = bits;
    }
}

// ---------------------------------------------------------------------------
// Merged pack: FC weights ballot + per-tap weight popcounts + BN thresholds.
__global__ void pack_misc_kernel(const uint32_t* __restrict__ wpk,
                                 const float* __restrict__ fcw,
                                 const float* __restrict__ p0, const float* __restrict__ p1,
                                 const float* __restrict__ p2, const float* __restrict__ p3,
                                 const float* __restrict__ p4, const float* __restrict__ p5,
                                 int* __restrict__ pw, float2* __restrict__ th,
                                 uint32_t* __restrict__ fcpk)
{
    int idx = blockIdx.x * blockDim.x + threadIdx.x;
    if (idx < 163840) {
        int warp = idx >> 5;
        int lane = idx & 31;
        int wi = warp & 31; int r = warp >> 5;
        int s = r & 15; int o = r >> 4;
        int c = wi * 32 + lane;
        float v = (c < 973) ? fcw[(size_t)o * 15568 + c * 16 + s] : 0.f;
        uint32_t bits = __ballot_sync(0xFFFFFFFFu, v > 0.f);
        if (lane == 0) fcpk[warp] = bits;
    } else if (idx < 163840 + 41472) {
        int i1 = idx - 163840;
        const int cum9[7]  = {0, 3456, 6912, 13824, 20736, 32256, 41472};
        const int woff[6]  = {0, 3456, 44928, 127872, 293760, 570240};
        const int winp[6]  = {1, 12, 12, 24, 24, 40};
        int l = 0;
#pragma unroll
        for (int i = 1; i < 6; ++i) if (i1 >= cum9[i]) l = i;
        int t = i1 - cum9[l];
        int cl  = t & 31;  t >>= 5;
        int tap = t % 9;
        int wi  = t / 9;
        const int WINP = winp[l];
        const uint32_t* src = wpk + woff[l] + (((size_t)wi * 9 + tap) * 32 + cl) * WINP;
        int s = 0;
        for (int q = 0; q < WINP; ++q) s += __popc(src[q]);
        pw[i1] = s;
    } else if (idx < 163840 + 41472 + 4608) {
        int i2 = idx - 163840 - 41472;
        const int cum[7]  = {0, 384, 768, 1536, 2304, 3584, 4608};
        const int cout[6] = {344, 352, 686, 679, 1246, 973};
        int l = 0;
#pragma unroll
        for (int i = 1; i < 6; ++i) if (i2 >= cum[i]) l = i;
        const float* p = (l == 0) ? p0 : (l == 1) ? p1 : (l == 2) ? p2
                        : (l == 3) ? p3 : (l == 4) ? p4 : p5;
        int c = i2 - cum[l];
        int Co = cout[l];
        float2 t;
        if (c < Co) {
            float gg = p[c], bb = p[Co + c], mm = p[2 * Co + c], vv = p[3 * Co + c];
            float sc = gg * rsqrtf(vv + 1e-5f);
            t.x = sc; t.y = bb - mm * sc;
        } else {
            t.x = 0.f; t.y = -1.f;
        }
        th[i2] = t;
    }
}

// ---------------------------------------------------------------------------
// Layer 0 (Cin=3, WINP=1): ALL 12 cout-words per block, halo in registers.
// Amortizes x-fill and weight-fill 12x vs the generic kernel.
__global__ void __launch_bounds__(256, 4)
bconv0_kernel(const uint32_t* __restrict__ in, uint8_t* __restrict__ out,
              const uint32_t* __restrict__ wpk, const int* __restrict__ pw,
              const float2* __restrict__ thg, int one)
{
    const int H = 32, W = 32, Cin = 3, WOUTP = 12;
    __shared__ uint32_t sw[3456];
    __shared__ int spw[3456];
    __shared__ float2 sth[384];
    __shared__ uint32_t sx[100];
    const int tid = threadIdx.x;
    const int x0 = (blockIdx.x & 3) * 8;
    const int y0 = (blockIdx.x >> 2) * 8;

    for (int i = tid; i < 3456; i += 256) { sw[i] = wpk[i]; spw[i] = pw[i]; }
    for (int i = tid; i < 384; i += 256) sth[i] = thg[i];

    const int g  = tid >> 6;
    const int p  = tid & 63;
    const int py = p >> 3, px = p & 7;
    const int y  = y0 + py, x = x0 + px;
    const bool eT = (y == 0), eB = (y == H - 1), eL = (x == 0), eR = (x == W - 1);
    const bool edge = eT | eB | eL | eR;
    const int nvCin = (3 - (int)eT - (int)eB) * (3 - (int)eL - (int)eR) * Cin;

    for (int it = 0; it < IMGS_PER_BLK; ++it) {
        const int n = blockIdx.y * IMGS_PER_BLK + it;
        __syncthreads();
        const uint32_t* ibase = in + (size_t)n * 1024;
        if (tid < 100) {
            const int iy = y0 + tid / 10 - 1;
            const int ix = x0 + tid % 10 - 1;
            sx[tid] = (iy >= 0 && iy < H && ix >= 0 && ix < W) ? ibase[iy * W + ix] : 0u;
        }
        __syncthreads();

        uint32_t xv[9];
#pragma unroll
        for (int t9 = 0; t9 < 9; ++t9)
            xv[t9] = sx[(py + t9 / 3) * 10 + (px + t9 % 3)];

        const size_t obase = ((size_t)n * 1024 + (size_t)y * W + x) * WOUTP * 4;
#pragma unroll 1
        for (int wi = 0; wi < 12; ++wi) {
            int D[8];
#pragma unroll
            for (int j = 0; j < 8; ++j) D[j] = 0;
#pragma unroll
            for (int t9 = 0; t9 < 9; ++t9) {
                const uint32_t* wb = &sw[(wi * 9 + t9) * 32 + g * 8];
#pragma unroll
                for (int j = 0; j < 8; ++j)
                    madacc(D[j], __popc(xv[t9] ^ wb[j]), one);
            }
            unsigned bytev = 0u;
#pragma unroll
            for (int j = 0; j < 8; ++j) {
                int corr = 0;
                if (edge) {
#pragma unroll
                    for (int ky = 0; ky < 3; ++ky)
#pragma unroll
                        for (int kx = 0; kx < 3; ++kx) {
                            const bool inv = (eT && ky == 0) || (eB && ky == 2)
                                          || (eL && kx == 0) || (eR && kx == 2);
                            if (inv) corr += spw[(wi * 9 + ky * 3 + kx) * 32 + g * 8 + j];
                        }
                }
                const int idot = nvCin - 2 * D[j] + 2 * corr;
                const float2 t = sth[wi * 32 + g * 8 + j];
                if (fmaf((float)idot, t.x, t.y) > 0.0f) bytev |= 1u << j;
            }
            out[obase + wi * 4 + g] = (uint8_t)bytev;
        }
    }
}

// ---------------------------------------------------------------------------
// Binary conv 3x3 pad 1, branch-free all-9-taps + edge correction, CSA popc,
// fma-pipe accumulation, kx unrolled. POOL=1: fused 2x2 maxpool epilogue
// (intra-warp shfl ORs; writer lane = even (py,px)); pad words zeroed by the
// wi==0, g==0 writer lanes.
template <int WINP, int POOL>
__global__ void __launch_bounds__(256, 4)
bconv_kernel(const uint32_t* __restrict__ in, uint8_t* __restrict__ out,
             const uint32_t* __restrict__ wpk, const int* __restrict__ pw,
             const float2* __restrict__ th,
             int H, int W, int Cin, int WOUTP, int tilesX, int one, int two,
             int padA, int padB)
{
    extern __shared__ uint32_t sm[];
    uint32_t* sw  = sm;                           // 9*32*WINP
    int*      spw = (int*)(sm + 9 * 32 * WINP);   // 9*32
    uint32_t* sx  = sm + 9 * 32 * WINP + 288;     // 10*10*WINP
    const int tid = threadIdx.x;
    const int wi = blockIdx.y;
    const int x0 = (blockIdx.x % tilesX) * 8;
    const int y0 = (blockIdx.x / tilesX) * 8;

    const uint32_t* wsrc = wpk + (size_t)wi * (9 * 32 * WINP);
    for (int i = tid; i < 9 * 32 * WINP; i += 256) sw[i] = wsrc[i];
    if (tid < 288) spw[tid] = pw[(size_t)wi * 288 + tid];
    { int i2 = tid + 256; if (i2 < 288) spw[i2] = pw[(size_t)wi * 288 + i2]; }

    const int g  = tid >> 6;
    const int p  = tid & 63;
    const int py = p >> 3;
    const int px = p & 7;

    for (int it = 0; it < IMGS_PER_BLK; ++it) {
        const int n = blockIdx.z * IMGS_PER_BLK + it;
        __syncthreads();
        const uint32_t* ibase = in + (size_t)n * H * W * WINP;
        for (int i = tid; i < 100 * WINP; i += 256) {
            const int w  = i % WINP;
            const int pp = i / WINP;
            const int iy = y0 + pp / 10 - 1;
            const int ix = x0 + pp % 10 - 1;
            uint32_t v = 0u;
            if (iy >= 0 && iy < H && ix >= 0 && ix < W)
                v = ibase[((size_t)iy * W + ix) * WINP + w];
            sx[i] = v;
        }
        __syncthreads();

        int D[8];
#pragma unroll
        for (int j = 0; j < 8; ++j) D[j] = 0;

#pragma unroll 1
        for (int ky = 0; ky < 3; ++ky) {
            const uint32_t* xrow = &sx[((py + ky) * 10 + px) * WINP];
            const uint32_t* wrow = &sw[(ky * 3 * 32 + g * 8) * WINP];
#pragma unroll
            for (int kx = 0; kx < 3; ++kx) {
                const uint32_t* xp = xrow + kx * WINP;
                const uint32_t* wp = wrow + kx * 32 * WINP;
#pragma unroll
                for (int t3 = 0; t3 < WINP / 12; ++t3) {
                    const uint4 x0v = *(const uint4*)(xp + t3 * 12);
                    const uint4 x1v = *(const uint4*)(xp + t3 * 12 + 4);
                    const uint4 x2v = *(const uint4*)(xp + t3 * 12 + 8);
#pragma unroll
                    for (int j = 0; j < 8; ++j) {
                        const uint32_t* wj = wp + j * WINP + t3 * 12;
                        const uint4 w0v = *(const uint4*)(wj);
                        const uint4 w1v = *(const uint4*)(wj + 4);
                        const uint4 w2v = *(const uint4*)(wj + 8);
                        uint32_t a, b, c;
                        uint32_t s0, s1, s2, s3, m0, m1, m2, m3;
                        a = x0v.x ^ w0v.x; b = x1v.x ^ w1v.x; c = x2v.x ^ w2v.x;
                        s0 = a ^ b ^ c; m0 = (a & b) | (c & (a | b));
                        a = x0v.y ^ w0v.y; b = x1v.y ^ w1v.y; c = x2v.y ^ w2v.y;
                        s1 = a ^ b ^ c; m1 = (a & b) | (c & (a | b));
                        a = x0v.z ^ w0v.z; b = x1v.z ^ w1v.z; c = x2v.z ^ w2v.z;
                        s2 = a ^ b ^ c; m2 = (a & b) | (c & (a | b));
                        a = x0v.w ^ w0v.w; b = x1v.w ^ w1v.w; c = x2v.w ^ w2v.w;
                        s3 = a ^ b ^ c; m3 = (a & b) | (c & (a | b));
                        madacc(D[j], __popc(s0), one);
                        madacc(D[j], __popc(s1), one);
                        madacc(D[j], __popc(s2), one);
                        madacc(D[j], __popc(s3), one);
                        madacc(D[j], __popc(m0), two);
                        madacc(D[j], __popc(m1), two);
                        madacc(D[j], __popc(m2), two);
                        madacc(D[j], __popc(m3), two);
                    }
                }
                if (WINP - (WINP / 12) * 12 == 4) {   // WINP=40 leftover uint4
                    const uint4 xv = *(const uint4*)(xp + (WINP / 12) * 12);
#pragma unroll
                    for (int j = 0; j < 8; ++j) {
                        const uint4 wv = *(const uint4*)(wp + j * WINP + (WINP / 12) * 12);
                        madacc(D[j], __popc(xv.x ^ wv.x), one);
                        madacc(D[j], __popc(xv.y ^ wv.y), one);
                        madacc(D[j], __popc(xv.z ^ wv.z), one);
                        madacc(D[j], __popc(xv.w ^ wv.w), one);
                    }
                }
            }
        }

        const int y = y0 + py, x = x0 + px;
        const bool eT = (y == 0), eB = (y == H - 1), eL = (x == 0), eR = (x == W - 1);
        const bool edge = eT | eB | eL | eR;
        const int nvCin = (3 - (int)eT - (int)eB) * (3 - (int)eL - (int)eR) * Cin;
        unsigned bytev = 0u;
#pragma unroll
        for (int j = 0; j < 8; ++j) {
            int corr = 0;
            if (edge) {
#pragma unroll
                for (int ky = 0; ky < 3; ++ky)
#pragma unroll
                    for (int kx = 0; kx < 3; ++kx) {
                        const bool inv = (eT && ky == 0) || (eB && ky == 2)
                                      || (eL && kx == 0) || (eR && kx == 2);
                        if (inv) corr += spw[(ky * 3 + kx) * 32 + g * 8 + j];
                    }
            }
            const int idot = nvCin - 2 * D[j] + 2 * corr;
            const float2 t = __ldg(&th[wi * 32 + g * 8 + j]);
            if (fmaf((float)idot, t.x, t.y) > 0.0f) bytev |= 1u << j;
        }

        if (POOL) {
            unsigned pb = bytev;
            pb |= __shfl_xor_sync(0xFFFFFFFFu, pb, 1);   // px partner
            pb |= __shfl_xor_sync(0xFFFFFFFFu, pb, 8);   // py partner
            if (((py | px) & 1) == 0) {
                const int Ho = H >> 1, Wo = W >> 1;
                const size_t base = (((size_t)n * Ho + (y >> 1)) * Wo + (x >> 1)) * WOUTP;
                out[base * 4 + wi * 4 + g] = (uint8_t)pb;
                if (wi == 0 && g == 0) {
                    uint32_t* o32 = (uint32_t*)out;
                    if (padA >= 0) o32[base + padA] = 0u;
                    if (padB >= 0) o32[base + padB] = 0u;
                }
            }
        } else {
            out[(((size_t)n * H * W + (size_t)y * W + x) * WOUTP + wi) * 4 + g]
                = (uint8_t)bytev;
        }
    }
}

// Binary FC: out[n][o] = 15568 - 2*popc(x ^ w) + fcb[o]
__global__ void fc_kernel(const uint32_t* __restrict__ xb, const uint32_t* __restrict__ wb,
                          const float* __restrict__ fcb, float* __restrict__ out)
{
    int t = blockIdx.x * blockDim.x + threadIdx.x;
    if (t >= NIMG * 10) return;
    int n = t / 10, o = t - n * 10;
    const uint4* xa = (const uint4*)(xb + (size_t)n * 512);
    const uint4* wa = (const uint4*)(wb + (size_t)o * 512);
    int D = 0;
#pragma unroll 8
    for (int i = 0; i < 128; ++i) {
        uint4 a = xa[i], b = wa[i];
        D += __popc(a.x ^ b.x) + __popc(a.y ^ b.y) + __popc(a.z ^ b.z) + __popc(a.w ^ b.w);
    }
    out[t] = (float)(15568 - 2 * D) + fcb[o];
}

// ---------------------------------------------------------------------------
extern "C" void kernel_launch(void* const* d_in, const int* in_sizes, int n_in,
                              void* d_out, int out_size)
{
    static const int s_cin[6]   = {3, 344, 352, 686, 679, 1246};
    static const int s_H[6]     = {32, 32, 16, 16, 8, 8};
    static const int s_winp[6]  = {1, 12, 12, 24, 24, 40};
    static const int s_woutp[6] = {12, 12, 24, 24, 40, 32};   // storage strides
    static const int s_gy[6]    = {12, 11, 24, 22, 40, 31};   // computed groups
    static const size_t s_woff[6] = {0, 3456, 44928, 127872, 293760, 570240};
    static const size_t s_toff[6] = {0, 384, 768, 1536, 2304, 3584};

    const long long szw[6] = {344LL*3*9, 352LL*344*9, 686LL*352*9,
                              679LL*686*9, 1246LL*679*9, 973LL*1246*9};
    const long long szp[6] = {4LL*344, 4LL*352, 4LL*686, 4LL*679, 4LL*1246, 4LL*973};
    auto find = [&](long long s) -> const void* {
        for (int i = 0; i < n_in; ++i)
            if ((long long)in_sizes[i] == s) return d_in[i];
        return (const void*)0;
    };
    const float* x   = (const float*)find(256LL * 3 * 32 * 32);
    const float* fcw = (const float*)find(10LL * 15568);
    const float* fcb = (const float*)find(10);
    const float* w[6]; const float* p[6];
    for (int i = 0; i < 6; ++i) {
        w[i] = (const float*)find(szw[i]);
        p[i] = (const float*)find(szp[i]);
    }
    if (!x || !fcw || !fcb) return;

    void *pA, *pB, *pW, *pPW, *pT, *pF;
    cudaGetSymbolAddress(&pA, g_bufA);
    cudaGetSymbolAddress(&pB, g_bufB);
    cudaGetSymbolAddress(&pW, g_wpk);
    cudaGetSymbolAddress(&pPW, g_wpw);
    cudaGetSymbolAddress(&pT, g_th);
    cudaGetSymbolAddress(&pF, g_fcpk);
    uint32_t* bufA = (uint32_t*)pA;
    uint32_t* bufB = (uint32_t*)pB;
    uint32_t* wpk  = (uint32_t*)pW;
    int*      wpw  = (int*)pPW;
    float2*   th   = (float2*)pT;
    uint32_t* fcpk = (uint32_t*)pF;

    auto smemFor = [](int winp) { return (size_t)(9 * 32 * winp + 288 + 100 * winp) * 4; };
    cudaFuncSetAttribute(bconv_kernel<40,1>, cudaFuncAttributeMaxDynamicSharedMemorySize, (int)smemFor(40));

    // --- pack phase: 2 launches ---
    {
        int tot = NIMG * 1024 + 104320 * 32;
        pack_xw_kernel<<<(tot + 255) / 256, 256>>>(x, w[0], w[1], w[2], w[3], w[4], w[5],
                                                   bufA, wpk);
    }
    {
        int tot = 163840 + 41472 + 4608;
        pack_misc_kernel<<<(tot + 255) / 256, 256>>>(wpk, fcw, p[0], p[1], p[2], p[3], p[4], p[5],
                                                     wpw, th, fcpk);
    }

    // --- conv stack ---
    auto conv = [&](int l, const uint32_t* src, uint32_t* dst, int pool,
                    int padA, int padB) {
        int H = s_H[l], W = H;
        int WINP = s_winp[l], WOUTP = s_woutp[l], Cin = s_cin[l];
        int tilesX = W / 8;
        dim3 grid((unsigned)((H / 8) * tilesX), (unsigned)s_gy[l],
                  (unsigned)(NIMG / IMGS_PER_BLK));
        size_t smem = smemFor(WINP);
        uint8_t* ob = (uint8_t*)dst;
        const uint32_t* wb = wpk + s_woff[l];
        const int* pwb = wpw + s_toff[l] * 9;
        const float2* tb = th + s_toff[l];
        if (pool) {
            switch (WINP) {
                case 12: bconv_kernel<12,1><<<grid, 256, smem>>>(src, ob, wb, pwb, tb, H, W, Cin, WOUTP, tilesX, 1, 2, padA, padB); break;
                case 24: bconv_kernel<24,1><<<grid, 256, smem>>>(src, ob, wb, pwb, tb, H, W, Cin, WOUTP, tilesX, 1, 2, padA, padB); break;
                case 40: bconv_kernel<40,1><<<grid, 256, smem>>>(src, ob, wb, pwb, tb, H, W, Cin, WOUTP, tilesX, 1, 2, padA, padB); break;
            }
        } else {
            switch (WINP) {
                case 12: bconv_kernel<12,0><<<grid, 256, smem>>>(src, ob, wb, pwb, tb, H, W, Cin, WOUTP, tilesX, 1, 2, -1, -1); break;
                case 24: bconv_kernel<24,0><<<grid, 256, smem>>>(src, ob, wb, pwb, tb, H, W, Cin, WOUTP, tilesX, 1, 2, -1, -1); break;
            }
        }
    };

    // conv0: specialized all-wi kernel.  bufA(x bits) -> bufB [32,32,12]
    bconv0_kernel<<<dim3(16, NIMG / IMGS_PER_BLK), 256>>>(
        bufA, (uint8_t*)bufB, wpk, wpw, th, 1);

    conv(1, bufB, bufA, 1, 11, -1);    // pooled -> A: [16,16,12], word 11 = 0
    conv(2, bufA, bufB, 0, -1, -1);    // B: [16,16,24] (pads via thresholds)
    conv(3, bufB, bufA, 1, 22, 23);    // pooled -> A: [8,8,24], words 22,23 = 0
    conv(4, bufA, bufB, 0, -1, -1);    // B: [8,8,40] (pads via thresholds)
    conv(5, bufB, bufA, 1, 31, -1);    // pooled -> A: [4,4,32], word 31 = 0

    // --- FC (reads pooled [4,4,32] = 512 words/img from bufA) ---
    fc_kernel<<<10, 256>>>(bufA, fcpk, fcb, (float*)d_out);
}

// round 15
// speedup vs baseline: 1.0023x; 1.0023x over previous
#include <cuda_runtime.h>
#include <cstdint>

#define NIMG 256
#define IMGS_PER_BLK 8

// Layers: cin {3,344,352,686,679,1246} cout {344,352,686,679,1246,973}
// conv H=W {32,32,16,16,8,8}, pool after 1,3,5
// WINP (storage stride) {1,12,12,24,24,40}, WOUTP stride {12,12,24,24,40,32}
// grid.y (computed cout groups, layers 1-5) {11,24,22,40,31}; pad groups of
// l1/l3/l5 are zero-filled by the following pool.
// Packed weight words/layer: cum {0,3456,44928,127872,293760,570240}, tot 938880

__device__ uint32_t g_bufA[(size_t)NIMG * 32 * 32 * 12];
__device__ uint32_t g_bufB[(size_t)NIMG * 32 * 32 * 12];
__device__ uint32_t g_wpk[938880];
__device__ int      g_wpw[41472];        // per (layer, wi, tap, cl): popc of weight row
__device__ float2   g_th[4608];          // per-channel (scale, beta - mean*scale)
__device__ uint32_t g_fcpk[10 * 16 * 32];

// Force IMAD (fma pipe) for accumulation; k is a runtime-opaque 1 or 2.
__device__ __forceinline__ void madacc(int& d, int p, int k) {
    asm("mad.lo.s32 %0, %1, %2, %0;" : "+r"(d) : "r"(p), "r"(k));
}

// ---------------------------------------------------------------------------
// Merged pack: x activations + all conv weights (warp per (layer,wi,cl,q),
// each thread reads 9 contiguous floats -> 9 ballots).
__global__ void pack_xw_kernel(const float* __restrict__ x,
                               const float* __restrict__ w0, const float* __restrict__ w1,
                               const float* __restrict__ w2, const float* __restrict__ w3,
                               const float* __restrict__ w4, const float* __restrict__ w5,
                               uint32_t* __restrict__ dstx, uint32_t* __restrict__ dstw)
{
    int idx = blockIdx.x * blockDim.x + threadIdx.x;
    if (idx < NIMG * 1024) {
        int n = idx >> 10, pix = idx & 1023;
        const float* xb = x + (size_t)n * 3 * 1024 + pix;
        uint32_t w = 0;
        if (xb[0]    > 0.f) w |= 1u;
        if (xb[1024] > 0.f) w |= 2u;
        if (xb[2048] > 0.f) w |= 4u;
        dstx[idx] = w;
        return;
    }
    const int cumw[7] = {0, 384, 4992, 14208, 32640, 63360, 104320};
    const int woff[6] = {0, 3456, 44928, 127872, 293760, 570240};
    const int cin[6]  = {3, 344, 352, 686, 679, 1246};
    const int cout[6] = {344, 352, 686, 679, 1246, 973};
    const int winp[6] = {1, 12, 12, 24, 24, 40};

    int wn = (idx >> 5) - 8192;
    int lane = idx & 31;
    if (wn >= 104320) return;

    int l = 0;
#pragma unroll
    for (int i = 1; i < 6; ++i) if (wn >= cumw[i]) l = i;

    const float* wsrc = (l == 0) ? w0 : (l == 1) ? w1 : (l == 2) ? w2
                       : (l == 3) ? w3 : (l == 4) ? w4 : w5;
    const int Ci = cin[l], Co = cout[l], WINP = winp[l];

    int widx = wn - cumw[l];
    int q  = widx % WINP;  widx /= WINP;
    int cl = widx & 31;
    int wi = widx >> 5;
    int co = wi * 32 + cl;
    int ci = q * 32 + lane;

    const bool valid = (co < Co && ci < Ci);
    const float* src = valid ? (wsrc + ((size_t)co * Ci + ci) * 9) : wsrc;
    uint32_t* dbase = dstw + woff[l] + ((size_t)wi * 9 * 32 + cl) * WINP + q;
#pragma unroll
    for (int tap = 0; tap < 9; ++tap) {
        float v = valid ? src[tap] : 0.f;
        uint32_t bits = __ballot_sync(0xFFFFFFFFu, valid && v > 0.f);
        if (lane == 0) dbase[(size_t)tap * 32 * WINP] = bits;
    }
}

// ---------------------------------------------------------------------------
// Merged pack: FC weights ballot + per-tap weight popcounts + BN thresholds.
__global__ void pack_misc_kernel(const uint32_t* __restrict__ wpk,
                                 const float* __restrict__ fcw,
                                 const float* __restrict__ p0, const float* __restrict__ p1,
                                 const float* __restrict__ p2, const float* __restrict__ p3,
                                 const float* __restrict__ p4, const float* __restrict__ p5,
                                 int* __restrict__ pw, float2* __restrict__ th,
                                 uint32_t* __restrict__ fcpk)
{
    int idx = blockIdx.x * blockDim.x + threadIdx.x;
    if (idx < 163840) {
        int warp = idx >> 5;
        int lane = idx & 31;
        int wi = warp & 31; int r = warp >> 5;
        int s = r & 15; int o = r >> 4;
        int c = wi * 32 + lane;
        float v = (c < 973) ? fcw[(size_t)o * 15568 + c * 16 + s] : 0.f;
        uint32_t bits = __ballot_sync(0xFFFFFFFFu, v > 0.f);
        if (lane == 0) fcpk[warp] = bits;
    } else if (idx < 163840 + 41472) {
        int i1 = idx - 163840;
        const int cum9[7]  = {0, 3456, 6912, 13824, 20736, 32256, 41472};
        const int woff[6]  = {0, 3456, 44928, 127872, 293760, 570240};
        const int winp[6]  = {1, 12, 12, 24, 24, 40};
        int l = 0;
#pragma unroll
        for (int i = 1; i < 6; ++i) if (i1 >= cum9[i]) l = i;
        int t = i1 - cum9[l];
        int cl  = t & 31;  t >>= 5;
        int tap = t % 9;
        int wi  = t / 9;
        const int WINP = winp[l];
        const uint32_t* src = wpk + woff[l] + (((size_t)wi * 9 + tap) * 32 + cl) * WINP;
        int s = 0;
        for (int q = 0; q < WINP; ++q) s += __popc(src[q]);
        pw[i1] = s;
    } else if (idx < 163840 + 41472 + 4608) {
        int i2 = idx - 163840 - 41472;
        const int cum[7]  = {0, 384, 768, 1536, 2304, 3584, 4608};
        const int cout[6] = {344, 352, 686, 679, 1246, 973};
        int l = 0;
#pragma unroll
        for (int i = 1; i < 6; ++i) if (i2 >= cum[i]) l = i;
        const float* p = (l == 0) ? p0 : (l == 1) ? p1 : (l == 2) ? p2
                        : (l == 3) ? p3 : (l == 4) ? p4 : p5;
        int c = i2 - cum[l];
        int Co = cout[l];
        float2 t;
        if (c < Co) {
            float gg = p[c], bb = p[Co + c], mm = p[2 * Co + c], vv = p[3 * Co + c];
            float sc = gg * rsqrtf(vv + 1e-5f);
            t.x = sc; t.y = bb - mm * sc;
        } else {
            t.x = 0.f; t.y = -1.f;
        }
        th[i2] = t;
    }
}

// ---------------------------------------------------------------------------
// Layer 0 (Cin=3, WINP=1): 6 cout-words per block (blockIdx.y selects half),
// halo in registers. 1024 blocks -> no grid starvation; fill amortized 6x.
__global__ void __launch_bounds__(256, 4)
bconv0_kernel(const uint32_t* __restrict__ in, uint8_t* __restrict__ out,
              const uint32_t* __restrict__ wpk, const int* __restrict__ pw,
              const float2* __restrict__ thg, int one)
{
    const int H = 32, W = 32, Cin = 3, WOUTP = 12;
    __shared__ uint32_t sw[1728];
    __shared__ int spw[1728];
    __shared__ float2 sth[192];
    __shared__ uint32_t sx[100];
    const int tid = threadIdx.x;
    const int x0 = (blockIdx.x & 3) * 8;
    const int y0 = (blockIdx.x >> 2) * 8;
    const int wiBase = blockIdx.y * 6;

    for (int i = tid; i < 1728; i += 256) {
        sw[i]  = wpk[wiBase * 288 + i];
        spw[i] = pw[wiBase * 288 + i];
    }
    if (tid < 192) sth[tid] = thg[wiBase * 32 + tid];

    const int g  = tid >> 6;
    const int p  = tid & 63;
    const int py = p >> 3, px = p & 7;
    const int y  = y0 + py, x = x0 + px;
    const bool eT = (y == 0), eB = (y == H - 1), eL = (x == 0), eR = (x == W - 1);
    const bool edge = eT | eB | eL | eR;
    const int nvCin = (3 - (int)eT - (int)eB) * (3 - (int)eL - (int)eR) * Cin;

    for (int it = 0; it < IMGS_PER_BLK; ++it) {
        const int n = blockIdx.z * IMGS_PER_BLK + it;
        __syncthreads();
        const uint32_t* ibase = in + (size_t)n * 1024;
        if (tid < 100) {
            const int iy = y0 + tid / 10 - 1;
            const int ix = x0 + tid % 10 - 1;
            sx[tid] = (iy >= 0 && iy < H && ix >= 0 && ix < W) ? ibase[iy * W + ix] : 0u;
        }
        __syncthreads();

        uint32_t xv[9];
#pragma unroll
        for (int t9 = 0; t9 < 9; ++t9)
            xv[t9] = sx[(py + t9 / 3) * 10 + (px + t9 % 3)];

        const size_t obase = ((size_t)n * 1024 + (size_t)y * W + x) * WOUTP * 4;
#pragma unroll 1
        for (int wiL = 0; wiL < 6; ++wiL) {
            int D[8];
#pragma unroll
            for (int j = 0; j < 8; ++j) D[j] = 0;
#pragma unroll
            for (int t9 = 0; t9 < 9; ++t9) {
                const uint32_t* wb = &sw[(wiL * 9 + t9) * 32 + g * 8];
#pragma unroll
                for (int j = 0; j < 8; ++j)
                    madacc(D[j], __popc(xv[t9] ^ wb[j]), one);
            }
            unsigned bytev = 0u;
#pragma unroll
            for (int j = 0; j < 8; ++j) {
                int corr = 0;
                if (edge) {
#pragma unroll
                    for (int ky = 0; ky < 3; ++ky)
#pragma unroll
                        for (int kx = 0; kx < 3; ++kx) {
                            const bool inv = (eT && ky == 0) || (eB && ky == 2)
                                          || (eL && kx == 0) || (eR && kx == 2);
                            if (inv) corr += spw[(wiL * 9 + ky * 3 + kx) * 32 + g * 8 + j];
                        }
                }
                const int idot = nvCin - 2 * D[j] + 2 * corr;
                const float2 t = sth[wiL * 32 + g * 8 + j];
                if (fmaf((float)idot, t.x, t.y) > 0.0f) bytev |= 1u << j;
            }
            out[obase + (wiBase + wiL) * 4 + g] = (uint8_t)bytev;
        }
    }
}

// ---------------------------------------------------------------------------
// Binary conv 3x3 pad 1, branch-free all-9-taps + edge correction, CSA popc,
// fma-pipe accumulation, kx unrolled. (Round-13 mainloop, unchanged.)
template <int WINP>
__global__ void __launch_bounds__(256, 4)
bconv_kernel(const uint32_t* __restrict__ in, uint8_t* __restrict__ out,
             const uint32_t* __restrict__ wpk, const int* __restrict__ pw,
             const float2* __restrict__ th,
             int H, int W, int Cin, int WOUTP, int tilesX, int one, int two)
{
    extern __shared__ uint32_t sm[];
    uint32_t* sw  = sm;                           // 9*32*WINP
    int*      spw = (int*)(sm + 9 * 32 * WINP);   // 9*32
    uint32_t* sx  = sm + 9 * 32 * WINP + 288;     // 10*10*WINP
    const int tid = threadIdx.x;
    const int wi = blockIdx.y;
    const int x0 = (blockIdx.x % tilesX) * 8;
    const int y0 = (blockIdx.x / tilesX) * 8;

    const uint32_t* wsrc = wpk + (size_t)wi * (9 * 32 * WINP);
    for (int i = tid; i < 9 * 32 * WINP; i += 256) sw[i] = wsrc[i];
    if (tid < 288) spw[tid] = pw[(size_t)wi * 288 + tid];
    { int i2 = tid + 256; if (i2 < 288) spw[i2] = pw[(size_t)wi * 288 + i2]; }

    const int g  = tid >> 6;
    const int p  = tid & 63;
    const int py = p >> 3;
    const int px = p & 7;

    for (int it = 0; it < IMGS_PER_BLK; ++it) {
        const int n = blockIdx.z * IMGS_PER_BLK + it;
        __syncthreads();
        const uint32_t* ibase = in + (size_t)n * H * W * WINP;
        for (int i = tid; i < 100 * WINP; i += 256) {
            const int w  = i % WINP;
            const int pp = i / WINP;
            const int iy = y0 + pp / 10 - 1;
            const int ix = x0 + pp % 10 - 1;
            uint32_t v = 0u;
            if (iy >= 0 && iy < H && ix >= 0 && ix < W)
                v = ibase[((size_t)iy * W + ix) * WINP + w];
            sx[i] = v;
        }
        __syncthreads();

        int D[8];
#pragma unroll
        for (int j = 0; j < 8; ++j) D[j] = 0;

#pragma unroll 1
        for (int ky = 0; ky < 3; ++ky) {
            const uint32_t* xrow = &sx[((py + ky) * 10 + px) * WINP];
            const uint32_t* wrow = &sw[(ky * 3 * 32 + g * 8) * WINP];
#pragma unroll
            for (int kx = 0; kx < 3; ++kx) {
                const uint32_t* xp = xrow + kx * WINP;
                const uint32_t* wp = wrow + kx * 32 * WINP;
#pragma unroll
                for (int t3 = 0; t3 < WINP / 12; ++t3) {
                    const uint4 x0v = *(const uint4*)(xp + t3 * 12);
                    const uint4 x1v = *(const uint4*)(xp + t3 * 12 + 4);
                    const uint4 x2v = *(const uint4*)(xp + t3 * 12 + 8);
#pragma unroll
                    for (int j = 0; j < 8; ++j) {
                        const uint32_t* wj = wp + j * WINP + t3 * 12;
                        const uint4 w0v = *(const uint4*)(wj);
                        const uint4 w1v = *(const uint4*)(wj + 4);
                        const uint4 w2v = *(const uint4*)(wj + 8);
                        uint32_t a, b, c;
                        uint32_t s0, s1, s2, s3, m0, m1, m2, m3;
                        a = x0v.x ^ w0v.x; b = x1v.x ^ w1v.x; c = x2v.x ^ w2v.x;
                        s0 = a ^ b ^ c; m0 = (a & b) | (c & (a | b));
                        a = x0v.y ^ w0v.y; b = x1v.y ^ w1v.y; c = x2v.y ^ w2v.y;
                        s1 = a ^ b ^ c; m1 = (a & b) | (c & (a | b));
                        a = x0v.z ^ w0v.z; b = x1v.z ^ w1v.z; c = x2v.z ^ w2v.z;
                        s2 = a ^ b ^ c; m2 = (a & b) | (c & (a | b));
                        a = x0v.w ^ w0v.w; b = x1v.w ^ w1v.w; c = x2v.w ^ w2v.w;
                        s3 = a ^ b ^ c; m3 = (a & b) | (c & (a | b));
                        madacc(D[j], __popc(s0), one);
                        madacc(D[j], __popc(s1), one);
                        madacc(D[j], __popc(s2), one);
                        madacc(D[j], __popc(s3), one);
                        madacc(D[j], __popc(m0), two);
                        madacc(D[j], __popc(m1), two);
                        madacc(D[j], __popc(m2), two);
                        madacc(D[j], __popc(m3), two);
                    }
                }
                if (WINP - (WINP / 12) * 12 == 4) {   // WINP=40 leftover uint4
                    const uint4 xv = *(const uint4*)(xp + (WINP / 12) * 12);
#pragma unroll
                    for (int j = 0; j < 8; ++j) {
                        const uint4 wv = *(const uint4*)(wp + j * WINP + (WINP / 12) * 12);
                        madacc(D[j], __popc(xv.x ^ wv.x), one);
                        madacc(D[j], __popc(xv.y ^ wv.y), one);
                        madacc(D[j], __popc(xv.z ^ wv.z), one);
                        madacc(D[j], __popc(xv.w ^ wv.w), one);
                    }
                }
            }
        }

        const int y = y0 + py, x = x0 + px;
        const bool eT = (y == 0), eB = (y == H - 1), eL = (x == 0), eR = (x == W - 1);
        const bool edge = eT | eB | eL | eR;
        const int nvCin = (3 - (int)eT - (int)eB) * (3 - (int)eL - (int)eR) * Cin;
        unsigned bytev = 0u;
#pragma unroll
        for (int j = 0; j < 8; ++j) {
            int corr = 0;
            if (edge) {
#pragma unroll
                for (int ky = 0; ky < 3; ++ky)
#pragma unroll
                    for (int kx = 0; kx < 3; ++kx) {
                        const bool inv = (eT && ky == 0) || (eB && ky == 2)
                                      || (eL && kx == 0) || (eR && kx == 2);
                        if (inv) corr += spw[(ky * 3 + kx) * 32 + g * 8 + j];
                    }
            }
            const int idot = nvCin - 2 * D[j] + 2 * corr;
            const float2 t = __ldg(&th[wi * 32 + g * 8 + j]);
            if (fmaf((float)idot, t.x, t.y) > 0.0f) bytev |= 1u << j;
        }
        out[(((size_t)n * H * W + (size_t)y * W + x) * WOUTP + wi) * 4 + g]
            = (uint8_t)bytev;
    }
}

// Maxpool 2x2 on packed bits == bitwise OR. Words w >= realW are written as 0.
__global__ void pool_kernel(const uint32_t* __restrict__ in, uint32_t* __restrict__ out,
                            int Ho, int Wo, int WORDS, int realW, int total)
{
    int idx = blockIdx.x * blockDim.x + threadIdx.x;
    if (idx >= total) return;
    int w = idx % WORDS; int r = idx / WORDS;
    int xo = r % Wo; r /= Wo;
    int yo = r % Ho; int n = r / Ho;
    if (w >= realW) { out[idx] = 0u; return; }
    const int Wi = Wo * 2;
    size_t base = (((size_t)n * (Ho * 2) + yo * 2) * Wi + xo * 2) * WORDS + w;
    size_t rs = (size_t)Wi * WORDS;
    out[idx] = in[base] | in[base + WORDS] | in[base + rs] | in[base + rs + WORDS];
}

// Binary FC: out[n][o] = 15568 - 2*popc(x ^ w) + fcb[o]
__global__ void fc_kernel(const uint32_t* __restrict__ xb, const uint32_t* __restrict__ wb,
                          const float* __restrict__ fcb, float* __restrict__ out)
{
    int t = blockIdx.x * blockDim.x + threadIdx.x;
    if (t >= NIMG * 10) return;
    int n = t / 10, o = t - n * 10;
    const uint4* xa = (const uint4*)(xb + (size_t)n * 512);
    const uint4* wa = (const uint4*)(wb + (size_t)o * 512);
    int D = 0;
#pragma unroll 8
    for (int i = 0; i < 128; ++i) {
        uint4 a = xa[i], b = wa[i];
        D += __popc(a.x ^ b.x) + __popc(a.y ^ b.y) + __popc(a.z ^ b.z) + __popc(a.w ^ b.w);
    }
    out[t] = (float)(15568 - 2 * D) + fcb[o];
}

// ---------------------------------------------------------------------------
extern "C" void kernel_launch(void* const* d_in, const int* in_sizes, int n_in,
                              void* d_out, int out_size)
{
    static const int s_cin[6]   = {3, 344, 352, 686, 679, 1246};
    static const int s_H[6]     = {32, 32, 16, 16, 8, 8};
    static const int s_winp[6]  = {1, 12, 12, 24, 24, 40};
    static const int s_woutp[6] = {12, 12, 24, 24, 40, 32};   // storage strides
    static const int s_gy[6]    = {12, 11, 24, 22, 40, 31};   // computed groups
    static const size_t s_woff[6] = {0, 3456, 44928, 127872, 293760, 570240};
    static const size_t s_toff[6] = {0, 384, 768, 1536, 2304, 3584};

    const long long szw[6] = {344LL*3*9, 352LL*344*9, 686LL*352*9,
                              679LL*686*9, 1246LL*679*9, 973LL*1246*9};
    const long long szp[6] = {4LL*344, 4LL*352, 4LL*686, 4LL*679, 4LL*1246, 4LL*973};
    auto find = [&](long long s) -> const void* {
        for (int i = 0; i < n_in; ++i)
            if ((long long)in_sizes[i] == s) return d_in[i];
        return (const void*)0;
    };
    const float* x   = (const float*)find(256LL * 3 * 32 * 32);
    const float* fcw = (const float*)find(10LL * 15568);
    const float* fcb = (const float*)find(10);
    const float* w[6]; const float* p[6];
    for (int i = 0; i < 6; ++i) {
        w[i] = (const float*)find(szw[i]);
        p[i] = (const float*)find(szp[i]);
    }
    if (!x || !fcw || !fcb) return;

    void *pA, *pB, *pW, *pPW, *pT, *pF;
    cudaGetSymbolAddress(&pA, g_bufA);
    cudaGetSymbolAddress(&pB, g_bufB);
    cudaGetSymbolAddress(&pW, g_wpk);
    cudaGetSymbolAddress(&pPW, g_wpw);
    cudaGetSymbolAddress(&pT, g_th);
    cudaGetSymbolAddress(&pF, g_fcpk);
    uint32_t* bufA = (uint32_t*)pA;
    uint32_t* bufB = (uint32_t*)pB;
    uint32_t* wpk  = (uint32_t*)pW;
    int*      wpw  = (int*)pPW;
    float2*   th   = (float2*)pT;
    uint32_t* fcpk = (uint32_t*)pF;

    auto smemFor = [](int winp) { return (size_t)(9 * 32 * winp + 288 + 100 * winp) * 4; };
    cudaFuncSetAttribute(bconv_kernel<40>, cudaFuncAttributeMaxDynamicSharedMemorySize, (int)smemFor(40));
    cudaFuncSetAttribute(bconv_kernel<24>, cudaFuncAttributeMaxDynamicSharedMemorySize, (int)smemFor(24));

    // --- pack phase: 2 launches ---
    {
        int tot = NIMG * 1024 + 104320 * 32;
        pack_xw_kernel<<<(tot + 255) / 256, 256>>>(x, w[0], w[1], w[2], w[3], w[4], w[5],
                                                   bufA, wpk);
    }
    {
        int tot = 163840 + 41472 + 4608;
        pack_misc_kernel<<<(tot + 255) / 256, 256>>>(wpk, fcw, p[0], p[1], p[2], p[3], p[4], p[5],
                                                     wpw, th, fcpk);
    }

    // --- conv stack ---
    auto conv = [&](int l, const uint32_t* src, uint32_t* dst) {
        int H = s_H[l], W = H;
        int WINP = s_winp[l], WOUTP = s_woutp[l], Cin = s_cin[l];
        int tilesX = W / 8;
        dim3 grid((unsigned)((H / 8) * tilesX), (unsigned)s_gy[l],
                  (unsigned)(NIMG / IMGS_PER_BLK));
        size_t smem = smemFor(WINP);
        uint8_t* ob = (uint8_t*)dst;
        const uint32_t* wb = wpk + s_woff[l];
        const int* pwb = wpw + s_toff[l] * 9;
        const float2* tb = th + s_toff[l];
        switch (WINP) {
            case 12: bconv_kernel<12><<<grid, 256, smem>>>(src, ob, wb, pwb, tb, H, W, Cin, WOUTP, tilesX, 1, 2); break;
            case 24: bconv_kernel<24><<<grid, 256, smem>>>(src, ob, wb, pwb, tb, H, W, Cin, WOUTP, tilesX, 1, 2); break;
            case 40: bconv_kernel<40><<<grid, 256, smem>>>(src, ob, wb, pwb, tb, H, W, Cin, WOUTP, tilesX, 1, 2); break;
        }
    };

    // conv0: specialized, 6 cout-words per block, grid = 16 x 2 x 32 = 1024 blocks
    bconv0_kernel<<<dim3(16, 2, NIMG / IMGS_PER_BLK), 256>>>(
        bufA, (uint8_t*)bufB, wpk, wpw, th, 1);

    conv(1, bufB, bufA);                                    // A: conv-space [32,32,12], groups 0..10
    {   int tot = NIMG * 16 * 16 * 12;
        pool_kernel<<<(tot + 255) / 256, 256>>>(bufA, bufB, 16, 16, 12, 11, tot); }  // B: [16,16,12]
    conv(2, bufB, bufA);                                    // A: [16,16,24] (pads via thresholds)
    conv(3, bufA, bufB);                                    // B: conv-space [16,16,24], groups 0..21
    {   int tot = NIMG * 8 * 8 * 24;
        pool_kernel<<<(tot + 255) / 256, 256>>>(bufB, bufA, 8, 8, 24, 22, tot); }    // A: [8,8,24]
    conv(4, bufA, bufB);                                    // B: [8,8,40] (pads via thresholds)
    conv(5, bufB, bufA);                                    // A: conv-space [8,8,32], groups 0..30
    {   int tot = NIMG * 4 * 4 * 32;
        pool_kernel<<<(tot + 255) / 256, 256>>>(bufA, bufB, 4, 4, 32, 31, tot); }    // B: [4,4,32]

    // --- FC ---
    fc_kernel<<<10, 256>>>(bufB, fcpk, fcb, (float*)d_out);
}

// round 16
// speedup vs baseline: 1.0368x; 1.0343x over previous
#include <cuda_runtime.h>
#include <cstdint>

#define NIMG 256
#define IMGS_PER_BLK 8

// Layers: cin {3,344,352,686,679,1246} cout {344,352,686,679,1246,973}
// conv H=W {32,32,16,16,8,8}, pool after 1,3,5
// WINP (storage stride) {1,12,12,24,24,40}; REALW (computed words)
// {1,11,11,22,22,39} — pad words skipped in compute (zero on both sides).
// grid.y (computed cout groups) {12,11,22,22,39,31}; pads of l2/l4 outputs
// zero-filled by zero_pads_kernel; pads of l1/l3/l5 by the pool.
// Packed weight words/layer: cum {0,3456,44928,127872,293760,570240}, tot 938880

__device__ uint32_t g_bufA[(size_t)NIMG * 32 * 32 * 12];
__device__ uint32_t g_bufB[(size_t)NIMG * 32 * 32 * 12];
__device__ uint32_t g_wpk[938880];
__device__ int      g_wpw[41472];        // per (layer, wi, tap, cl): popc of weight row
__device__ float2   g_th[4608];          // per-channel (scale, beta - mean*scale)
__device__ uint32_t g_fcpk[10 * 16 * 32];

// Force IMAD (fma pipe) for accumulation; k is a runtime-opaque 1 or 2.
__device__ __forceinline__ void madacc(int& d, int p, int k) {
    asm("mad.lo.s32 %0, %1, %2, %0;" : "+r"(d) : "r"(p), "r"(k));
}

// ---------------------------------------------------------------------------
// Merged pack: x activations + all conv weights (warp per (layer,wi,cl,q),
// each thread reads 9 contiguous floats -> 9 ballots).
__global__ void pack_xw_kernel(const float* __restrict__ x,
                               const float* __restrict__ w0, const float* __restrict__ w1,
                               const float* __restrict__ w2, const float* __restrict__ w3,
                               const float* __restrict__ w4, const float* __restrict__ w5,
                               uint32_t* __restrict__ dstx, uint32_t* __restrict__ dstw)
{
    int idx = blockIdx.x * blockDim.x + threadIdx.x;
    if (idx < NIMG * 1024) {
        int n = idx >> 10, pix = idx & 1023;
        const float* xb = x + (size_t)n * 3 * 1024 + pix;
        uint32_t w = 0;
        if (xb[0]    > 0.f) w |= 1u;
        if (xb[1024] > 0.f) w |= 2u;
        if (xb[2048] > 0.f) w |= 4u;
        dstx[idx] = w;
        return;
    }
    const int cumw[7] = {0, 384, 4992, 14208, 32640, 63360, 104320};
    const int woff[6] = {0, 3456, 44928, 127872, 293760, 570240};
    const int cin[6]  = {3, 344, 352, 686, 679, 1246};
    const int cout[6] = {344, 352, 686, 679, 1246, 973};
    const int winp[6] = {1, 12, 12, 24, 24, 40};

    int wn = (idx >> 5) - 8192;
    int lane = idx & 31;
    if (wn >= 104320) return;

    int l = 0;
#pragma unroll
    for (int i = 1; i < 6; ++i) if (wn >= cumw[i]) l = i;

    const float* wsrc = (l == 0) ? w0 : (l == 1) ? w1 : (l == 2) ? w2
                       : (l == 3) ? w3 : (l == 4) ? w4 : w5;
    const int Ci = cin[l], Co = cout[l], WINP = winp[l];

    int widx = wn - cumw[l];
    int q  = widx % WINP;  widx /= WINP;
    int cl = widx & 31;
    int wi = widx >> 5;
    int co = wi * 32 + cl;
    int ci = q * 32 + lane;

    const bool valid = (co < Co && ci < Ci);
    const float* src = valid ? (wsrc + ((size_t)co * Ci + ci) * 9) : wsrc;
    uint32_t* dbase = dstw + woff[l] + ((size_t)wi * 9 * 32 + cl) * WINP + q;
#pragma unroll
    for (int tap = 0; tap < 9; ++tap) {
        float v = valid ? src[tap] : 0.f;
        uint32_t bits = __ballot_sync(0xFFFFFFFFu, valid && v > 0.f);
        if (lane == 0) dbase[(size_t)tap * 32 * WINP] = bits;
    }
}

// ---------------------------------------------------------------------------
// Merged pack: FC weights ballot + per-tap weight popcounts + BN thresholds.
__global__ void pack_misc_kernel(const uint32_t* __restrict__ wpk,
                                 const float* __restrict__ fcw,
                                 const float* __restrict__ p0, const float* __restrict__ p1,
                                 const float* __restrict__ p2, const float* __restrict__ p3,
                                 const float* __restrict__ p4, const float* __restrict__ p5,
                                 int* __restrict__ pw, float2* __restrict__ th,
                                 uint32_t* __restrict__ fcpk)
{
    int idx = blockIdx.x * blockDim.x + threadIdx.x;
    if (idx < 163840) {
        int warp = idx >> 5;
        int lane = idx & 31;
        int wi = warp & 31; int r = warp >> 5;
        int s = r & 15; int o = r >> 4;
        int c = wi * 32 + lane;
        float v = (c < 973) ? fcw[(size_t)o * 15568 + c * 16 + s] : 0.f;
        uint32_t bits = __ballot_sync(0xFFFFFFFFu, v > 0.f);
        if (lane == 0) fcpk[warp] = bits;
    } else if (idx < 163840 + 41472) {
        int i1 = idx - 163840;
        const int cum9[7]  = {0, 3456, 6912, 13824, 20736, 32256, 41472};
        const int woff[6]  = {0, 3456, 44928, 127872, 293760, 570240};
        const int winp[6]  = {1, 12, 12, 24, 24, 40};
        int l = 0;
#pragma unroll
        for (int i = 1; i < 6; ++i) if (i1 >= cum9[i]) l = i;
        int t = i1 - cum9[l];
        int cl  = t & 31;  t >>= 5;
        int tap = t % 9;
        int wi  = t / 9;
        const int WINP = winp[l];
        const uint32_t* src = wpk + woff[l] + (((size_t)wi * 9 + tap) * 32 + cl) * WINP;
        int s = 0;
        for (int q = 0; q < WINP; ++q) s += __popc(src[q]);
        pw[i1] = s;
    } else if (idx < 163840 + 41472 + 4608) {
        int i2 = idx - 163840 - 41472;
        const int cum[7]  = {0, 384, 768, 1536, 2304, 3584, 4608};
        const int cout[6] = {344, 352, 686, 679, 1246, 973};
        int l = 0;
#pragma unroll
        for (int i = 1; i < 6; ++i) if (i2 >= cum[i]) l = i;
        const float* p = (l == 0) ? p0 : (l == 1) ? p1 : (l == 2) ? p2
                        : (l == 3) ? p3 : (l == 4) ? p4 : p5;
        int c = i2 - cum[l];
        int Co = cout[l];
        float2 t;
        if (c < Co) {
            float gg = p[c], bb = p[Co + c], mm = p[2 * Co + c], vv = p[3 * Co + c];
            float sc = gg * rsqrtf(vv + 1e-5f);
            t.x = sc; t.y = bb - mm * sc;
        } else {
            t.x = 0.f; t.y = -1.f;
        }
        th[i2] = t;
    }
}

// ---------------------------------------------------------------------------
// Binary conv 3x3 pad 1, branch-free all-9-taps + edge correction, CSA popc,
// fma-pipe accumulation, kx unrolled. REALW < WINP: channel-pad words are
// skipped in the compute (exact: pads are zero in both x and w).
template <int WINP, int REALW>
__global__ void __launch_bounds__(256, 4)
bconv_kernel(const uint32_t* __restrict__ in, uint8_t* __restrict__ out,
             const uint32_t* __restrict__ wpk, const int* __restrict__ pw,
             const float2* __restrict__ th,
             int H, int W, int Cin, int WOUTP, int tilesX, int one, int two)
{
    constexpr int FB = REALW / 12;        // full 12-word CSA blocks
    constexpr int L  = REALW - FB * 12;   // leftover real words (11, 10, 3, or 0)

    extern __shared__ uint32_t sm[];
    uint32_t* sw  = sm;                           // 9*32*WINP
    int*      spw = (int*)(sm + 9 * 32 * WINP);   // 9*32
    uint32_t* sx  = sm + 9 * 32 * WINP + 288;     // 10*10*WINP
    const int tid = threadIdx.x;
    const int wi = blockIdx.y;
    const int x0 = (blockIdx.x % tilesX) * 8;
    const int y0 = (blockIdx.x / tilesX) * 8;

    const uint32_t* wsrc = wpk + (size_t)wi * (9 * 32 * WINP);
    for (int i = tid; i < 9 * 32 * WINP; i += 256) sw[i] = wsrc[i];
    if (tid < 288) spw[tid] = pw[(size_t)wi * 288 + tid];
    { int i2 = tid + 256; if (i2 < 288) spw[i2] = pw[(size_t)wi * 288 + i2]; }

    const int g  = tid >> 6;
    const int p  = tid & 63;
    const int py = p >> 3;
    const int px = p & 7;

    for (int it = 0; it < IMGS_PER_BLK; ++it) {
        const int n = blockIdx.z * IMGS_PER_BLK + it;
        __syncthreads();
        const uint32_t* ibase = in + (size_t)n * H * W * WINP;
        for (int i = tid; i < 100 * WINP; i += 256) {
            const int w  = i % WINP;
            const int pp = i / WINP;
            const int iy = y0 + pp / 10 - 1;
            const int ix = x0 + pp % 10 - 1;
            uint32_t v = 0u;
            if (iy >= 0 && iy < H && ix >= 0 && ix < W)
                v = ibase[((size_t)iy * W + ix) * WINP + w];
            sx[i] = v;
        }
        __syncthreads();

        int D[8];
#pragma unroll
        for (int j = 0; j < 8; ++j) D[j] = 0;

#pragma unroll 1
        for (int ky = 0; ky < 3; ++ky) {
            const uint32_t* xrow = &sx[((py + ky) * 10 + px) * WINP];
            const uint32_t* wrow = &sw[(ky * 3 * 32 + g * 8) * WINP];
#pragma unroll
            for (int kx = 0; kx < 3; ++kx) {
                const uint32_t* xp = xrow + kx * WINP;
                const uint32_t* wp = wrow + kx * 32 * WINP;
                if (WINP == 1) {
                    const uint32_t xv = xp[0];
#pragma unroll
                    for (int j = 0; j < 8; ++j)
                        madacc(D[j], __popc(xv ^ wp[j]), one);
                } else {
#pragma unroll
                    for (int t3 = 0; t3 < FB; ++t3) {
                        const uint4 x0v = *(const uint4*)(xp + t3 * 12);
                        const uint4 x1v = *(const uint4*)(xp + t3 * 12 + 4);
                        const uint4 x2v = *(const uint4*)(xp + t3 * 12 + 8);
#pragma unroll
                        for (int j = 0; j < 8; ++j) {
                            const uint32_t* wj = wp + j * WINP + t3 * 12;
                            const uint4 w0v = *(const uint4*)(wj);
                            const uint4 w1v = *(const uint4*)(wj + 4);
                            const uint4 w2v = *(const uint4*)(wj + 8);
                            uint32_t a, b, c;
                            uint32_t s0, s1, s2, s3, m0, m1, m2, m3;
                            a = x0v.x ^ w0v.x; b = x1v.x ^ w1v.x; c = x2v.x ^ w2v.x;
                            s0 = a ^ b ^ c; m0 = (a & b) | (c & (a | b));
                            a = x0v.y ^ w0v.y; b = x1v.y ^ w1v.y; c = x2v.y ^ w2v.y;
                            s1 = a ^ b ^ c; m1 = (a & b) | (c & (a | b));
                            a = x0v.z ^ w0v.z; b = x1v.z ^ w1v.z; c = x2v.z ^ w2v.z;
                            s2 = a ^ b ^ c; m2 = (a & b) | (c & (a | b));
                            a = x0v.w ^ w0v.w; b = x1v.w ^ w1v.w; c = x2v.w ^ w2v.w;
                            s3 = a ^ b ^ c; m3 = (a & b) | (c & (a | b));
                            madacc(D[j], __popc(s0), one);
                            madacc(D[j], __popc(s1), one);
                            madacc(D[j], __popc(s2), one);
                            madacc(D[j], __popc(s3), one);
                            madacc(D[j], __popc(m0), two);
                            madacc(D[j], __popc(m1), two);
                            madacc(D[j], __popc(m2), two);
                            madacc(D[j], __popc(m3), two);
                        }
                    }
                    if (L == 11) {      // cols 0-2 CSA, col 3 = plain pair (skip pad word 11)
                        const uint32_t* xq = xp + FB * 12;
                        const uint4 x0v = *(const uint4*)(xq);
                        const uint4 x1v = *(const uint4*)(xq + 4);
                        const uint4 x2v = *(const uint4*)(xq + 8);
#pragma unroll
                        for (int j = 0; j < 8; ++j) {
                            const uint32_t* wj = wp + j * WINP + FB * 12;
                            const uint4 w0v = *(const uint4*)(wj);
                            const uint4 w1v = *(const uint4*)(wj + 4);
                            const uint4 w2v = *(const uint4*)(wj + 8);
                            uint32_t a, b, c, s0, s1, s2, m0, m1, m2;
                            a = x0v.x ^ w0v.x; b = x1v.x ^ w1v.x; c = x2v.x ^ w2v.x;
                            s0 = a ^ b ^ c; m0 = (a & b) | (c & (a | b));
                            a = x0v.y ^ w0v.y; b = x1v.y ^ w1v.y; c = x2v.y ^ w2v.y;
                            s1 = a ^ b ^ c; m1 = (a & b) | (c & (a | b));
                            a = x0v.z ^ w0v.z; b = x1v.z ^ w1v.z; c = x2v.z ^ w2v.z;
                            s2 = a ^ b ^ c; m2 = (a & b) | (c & (a | b));
                            madacc(D[j], __popc(s0), one);
                            madacc(D[j], __popc(s1), one);
                            madacc(D[j], __popc(s2), one);
                            madacc(D[j], __popc(m0), two);
                            madacc(D[j], __popc(m1), two);
                            madacc(D[j], __popc(m2), two);
                            madacc(D[j], __popc(x0v.w ^ w0v.w), one);
                            madacc(D[j], __popc(x1v.w ^ w1v.w), one);
                        }
                    }
                    if (L == 10) {      // cols 0,1 CSA; cols 2,3 plain pairs
                        const uint32_t* xq = xp + FB * 12;
                        const uint4 x0v = *(const uint4*)(xq);
                        const uint4 x1v = *(const uint4*)(xq + 4);
                        const uint4 x2v = *(const uint4*)(xq + 8);
#pragma unroll
                        for (int j = 0; j < 8; ++j) {
                            const uint32_t* wj = wp + j * WINP + FB * 12;
                            const uint4 w0v = *(const uint4*)(wj);
                            const uint4 w1v = *(const uint4*)(wj + 4);
                            const uint4 w2v = *(const uint4*)(wj + 8);
                            uint32_t a, b, c, s0, s1, m0, m1;
                            a = x0v.x ^ w0v.x; b = x1v.x ^ w1v.x; c = x2v.x ^ w2v.x;
                            s0 = a ^ b ^ c; m0 = (a & b) | (c & (a | b));
                            a = x0v.y ^ w0v.y; b = x1v.y ^ w1v.y; c = x2v.y ^ w2v.y;
                            s1 = a ^ b ^ c; m1 = (a & b) | (c & (a | b));
                            madacc(D[j], __popc(s0), one);
                            madacc(D[j], __popc(s1), one);
                            madacc(D[j], __popc(m0), two);
                            madacc(D[j], __popc(m1), two);
                            madacc(D[j], __popc(x0v.z ^ w0v.z), one);
                            madacc(D[j], __popc(x1v.z ^ w1v.z), one);
                            madacc(D[j], __popc(x0v.w ^ w0v.w), one);
                            madacc(D[j], __popc(x1v.w ^ w1v.w), one);
                        }
                    }
                    if (L == 3) {       // three plain words (skip pad word 3)
                        const uint4 xv = *(const uint4*)(xp + FB * 12);
#pragma unroll
                        for (int j = 0; j < 8; ++j) {
                            const uint4 wv = *(const uint4*)(wp + j * WINP + FB * 12);
                            madacc(D[j], __popc(xv.x ^ wv.x), one);
                            madacc(D[j], __popc(xv.y ^ wv.y), one);
                            madacc(D[j], __popc(xv.z ^ wv.z), one);
                        }
                    }
                }
            }
        }

        const int y = y0 + py, x = x0 + px;
        const bool eT = (y == 0), eB = (y == H - 1), eL = (x == 0), eR = (x == W - 1);
        const bool edge = eT | eB | eL | eR;
        const int nvCin = (3 - (int)eT - (int)eB) * (3 - (int)eL - (int)eR) * Cin;
        unsigned bytev = 0u;
#pragma unroll
        for (int j = 0; j < 8; ++j) {
            int corr = 0;
            if (edge) {
#pragma unroll
                for (int ky = 0; ky < 3; ++ky)
#pragma unroll
                    for (int kx = 0; kx < 3; ++kx) {
                        const bool inv = (eT && ky == 0) || (eB && ky == 2)
                                      || (eL && kx == 0) || (eR && kx == 2);
                        if (inv) corr += spw[(ky * 3 + kx) * 32 + g * 8 + j];
                    }
            }
            const int idot = nvCin - 2 * D[j] + 2 * corr;
            const float2 t = __ldg(&th[wi * 32 + g * 8 + j]);
            if (fmaf((float)idot, t.x, t.y) > 0.0f) bytev |= 1u << j;
        }
        out[(((size_t)n * H * W + (size_t)y * W + x) * WOUTP + wi) * 4 + g]
            = (uint8_t)bytev;
    }
}

// Maxpool 2x2 on packed bits == bitwise OR. Words w >= realW are written as 0.
__global__ void pool_kernel(const uint32_t* __restrict__ in, uint32_t* __restrict__ out,
                            int Ho, int Wo, int WORDS, int realW, int total)
{
    int idx = blockIdx.x * blockDim.x + threadIdx.x;
    if (idx >= total) return;
    int w = idx % WORDS; int r = idx / WORDS;
    int xo = r % Wo; r /= Wo;
    int yo = r % Ho; int n = r / Ho;
    if (w >= realW) { out[idx] = 0u; return; }
    const int Wi = Wo * 2;
    size_t base = (((size_t)n * (Ho * 2) + yo * 2) * Wi + xo * 2) * WORDS + w;
    size_t rs = (size_t)Wi * WORDS;
    out[idx] = in[base] | in[base + WORDS] | in[base + rs] | in[base + rs + WORDS];
}

// Zero pad cout-words of a conv output the conv no longer computes.
__global__ void zero_pads_kernel(uint32_t* __restrict__ out, int WORDS, int w0,
                                 int nw, int total)
{
    int idx = blockIdx.x * blockDim.x + threadIdx.x;
    if (idx >= total) return;
    int p = idx / nw, k = idx - p * nw;
    out[(size_t)p * WORDS + w0 + k] = 0u;
}

// Binary FC: out[n][o] = 15568 - 2*popc(x ^ w) + fcb[o]
__global__ void fc_kernel(const uint32_t* __restrict__ xb, const uint32_t* __restrict__ wb,
                          const float* __restrict__ fcb, float* __restrict__ out)
{
    int t = blockIdx.x * blockDim.x + threadIdx.x;
    if (t >= NIMG * 10) return;
    int n = t / 10, o = t - n * 10;
    const uint4* xa = (const uint4*)(xb + (size_t)n * 512);
    const uint4* wa = (const uint4*)(wb + (size_t)o * 512);
    int D = 0;
#pragma unroll 8
    for (int i = 0; i < 128; ++i) {
        uint4 a = xa[i], b = wa[i];
        D += __popc(a.x ^ b.x) + __popc(a.y ^ b.y) + __popc(a.z ^ b.z) + __popc(a.w ^ b.w);
    }
    out[t] = (float)(15568 - 2 * D) + fcb[o];
}

// ---------------------------------------------------------------------------
extern "C" void kernel_launch(void* const* d_in, const int* in_sizes, int n_in,
                              void* d_out, int out_size)
{
    static const int s_cin[6]   = {3, 344, 352, 686, 679, 1246};
    static const int s_H[6]     = {32, 32, 16, 16, 8, 8};
    static const int s_winp[6]  = {1, 12, 12, 24, 24, 40};
    static const int s_woutp[6] = {12, 12, 24, 24, 40, 32};   // storage strides
    static const int s_gy[6]    = {12, 11, 22, 22, 39, 31};   // computed groups
    static const size_t s_woff[6] = {0, 3456, 44928, 127872, 293760, 570240};
    static const size_t s_toff[6] = {0, 384, 768, 1536, 2304, 3584};

    const long long szw[6] = {344LL*3*9, 352LL*344*9, 686LL*352*9,
                              679LL*686*9, 1246LL*679*9, 973LL*1246*9};
    const long long szp[6] = {4LL*344, 4LL*352, 4LL*686, 4LL*679, 4LL*1246, 4LL*973};
    auto find = [&](long long s) -> const void* {
        for (int i = 0; i < n_in; ++i)
            if ((long long)in_sizes[i] == s) return d_in[i];
        return (const void*)0;
    };
    const float* x   = (const float*)find(256LL * 3 * 32 * 32);
    const float* fcw = (const float*)find(10LL * 15568);
    const float* fcb = (const float*)find(10);
    const float* w[6]; const float* p[6];
    for (int i = 0; i < 6; ++i) {
        w[i] = (const float*)find(szw[i]);
        p[i] = (const float*)find(szp[i]);
    }
    if (!x || !fcw || !fcb) return;

    void *pA, *pB, *pW, *pPW, *pT, *pF;
    cudaGetSymbolAddress(&pA, g_bufA);
    cudaGetSymbolAddress(&pB, g_bufB);
    cudaGetSymbolAddress(&pW, g_wpk);
    cudaGetSymbolAddress(&pPW, g_wpw);
    cudaGetSymbolAddress(&pT, g_th);
    cudaGetSymbolAddress(&pF, g_fcpk);
    uint32_t* bufA = (uint32_t*)pA;
    uint32_t* bufB = (uint32_t*)pB;
    uint32_t* wpk  = (uint32_t*)pW;
    int*      wpw  = (int*)pPW;
    float2*   th   = (float2*)pT;
    uint32_t* fcpk = (uint32_t*)pF;

    auto smemFor = [](int winp) { return (size_t)(9 * 32 * winp + 288 + 100 * winp) * 4; };
    cudaFuncSetAttribute(bconv_kernel<40,39>, cudaFuncAttributeMaxDynamicSharedMemorySize, (int)smemFor(40));
    cudaFuncSetAttribute(bconv_kernel<24,22>, cudaFuncAttributeMaxDynamicSharedMemorySize, (int)smemFor(24));

    // --- pack phase: 2 launches ---
    {
        int tot = NIMG * 1024 + 104320 * 32;
        pack_xw_kernel<<<(tot + 255) / 256, 256>>>(x, w[0], w[1], w[2], w[3], w[4], w[5],
                                                   bufA, wpk);
    }
    {
        int tot = 163840 + 41472 + 4608;
        pack_misc_kernel<<<(tot + 255) / 256, 256>>>(wpk, fcw, p[0], p[1], p[2], p[3], p[4], p[5],
                                                     wpw, th, fcpk);
    }

    // --- conv stack ---
    auto conv = [&](int l, const uint32_t* src, uint32_t* dst) {
        int H = s_H[l], W = H;
        int WINP = s_winp[l], WOUTP = s_woutp[l], Cin = s_cin[l];
        int tilesX = W / 8;
        dim3 grid((unsigned)((H / 8) * tilesX), (unsigned)s_gy[l],
                  (unsigned)(NIMG / IMGS_PER_BLK));
        size_t smem = smemFor(WINP);
        uint8_t* ob = (uint8_t*)dst;
        const uint32_t* wb = wpk + s_woff[l];
        const int* pwb = wpw + s_toff[l] * 9;
        const float2* tb = th + s_toff[l];
        switch (l) {
            case 0:           bconv_kernel<1,1>  <<<grid, 256, smem>>>(src, ob, wb, pwb, tb, H, W, Cin, WOUTP, tilesX, 1, 2); break;
            case 1: case 2:   bconv_kernel<12,11><<<grid, 256, smem>>>(src, ob, wb, pwb, tb, H, W, Cin, WOUTP, tilesX, 1, 2); break;
            case 3: case 4:   bconv_kernel<24,22><<<grid, 256, smem>>>(src, ob, wb, pwb, tb, H, W, Cin, WOUTP, tilesX, 1, 2); break;
            case 5:           bconv_kernel<40,39><<<grid, 256, smem>>>(src, ob, wb, pwb, tb, H, W, Cin, WOUTP, tilesX, 1, 2); break;
        }
    };

    conv(0, bufA, bufB);                                    // B: [32,32,12]
    conv(1, bufB, bufA);                                    // A: conv-space [32,32,12], groups 0..10
    {   int tot = NIMG * 16 * 16 * 12;
        pool_kernel<<<(tot + 255) / 256, 256>>>(bufA, bufB, 16, 16, 12, 11, tot); }  // B: [16,16,12]
    {   int tot = NIMG * 16 * 16 * 2;   // zero l2 output pad words 22,23 of bufA
        zero_pads_kernel<<<(tot + 255) / 256, 256>>>(bufA, 24, 22, 2, tot); }
    conv(2, bufB, bufA);                                    // A: [16,16,24], groups 0..21
    conv(3, bufA, bufB);                                    // B: conv-space [16,16,24], groups 0..21
    {   int tot = NIMG * 8 * 8 * 24;
        pool_kernel<<<(tot + 255) / 256, 256>>>(bufB, bufA, 8, 8, 24, 22, tot); }    // A: [8,8,24]
    {   int tot = NIMG * 8 * 8;          // zero l4 output pad word 39 of bufB
        zero_pads_kernel<<<(tot + 255) / 256, 256>>>(bufB, 40, 39, 1, tot); }
    conv(4, bufA, bufB);                                    // B: [8,8,40], groups 0..38
    conv(5, bufB, bufA);                                    // A: conv-space [8,8,32], groups 0..30
    {   int tot = NIMG * 4 * 4 * 32;
        pool_kernel<<<(tot + 255) / 256, 256>>>(bufA, bufB, 4, 4, 32, 31, tot); }    // B: [4,4,32]

    // --- FC ---
    fc_kernel<<<10, 256>>>(bufB, fcpk, fcb, (float*)d_out);
}

// round 17
// speedup vs baseline: 1.0650x; 1.0272x over previous
#include <cuda_runtime.h>
#include <cstdint>

#define NIMG 256
#define IMGS_PER_BLK 8

// Layers: cin {3,344,352,686,679,1246} cout {344,352,686,679,1246,973}
// conv H=W {32,32,16,16,8,8}, pool after 1,3,5
// WINP (storage stride) {1,12,12,24,24,40}; REALW {1,11,11,22,22,39} (pads
// skipped in compute). grid.y {12,11,22,22,39,31}; output pads of l2/l4 via
// zero_pads_kernel, of l1/l3/l5 via the pool.
// Packed weight words/layer: cum {0,3456,44928,127872,293760,570240}, tot 938880

__device__ uint32_t g_bufA[(size_t)NIMG * 32 * 32 * 12];
__device__ uint32_t g_bufB[(size_t)NIMG * 32 * 32 * 12];
__device__ uint32_t g_wpk[938880];
__device__ int      g_wpw[41472];        // per (layer, wi, tap, cl): popc of weight row
__device__ float2   g_th[4608];          // per-channel (scale, beta - mean*scale)
__device__ uint32_t g_fcpk[10 * 16 * 32];

// Force IMAD (fma pipe) for accumulation; k is a runtime-opaque 1 or 2.
__device__ __forceinline__ void madacc(int& d, int p, int k) {
    asm("mad.lo.s32 %0, %1, %2, %0;" : "+r"(d) : "r"(p), "r"(k));
}

// ---------------------------------------------------------------------------
// Merged pack: x activations + all conv weights (warp per (layer,wi,cl,q),
// each thread reads 9 contiguous floats -> 9 ballots).
__global__ void pack_xw_kernel(const float* __restrict__ x,
                               const float* __restrict__ w0, const float* __restrict__ w1,
                               const float* __restrict__ w2, const float* __restrict__ w3,
                               const float* __restrict__ w4, const float* __restrict__ w5,
                               uint32_t* __restrict__ dstx, uint32_t* __restrict__ dstw)
{
    int idx = blockIdx.x * blockDim.x + threadIdx.x;
    if (idx < NIMG * 1024) {
        int n = idx >> 10, pix = idx & 1023;
        const float* xb = x + (size_t)n * 3 * 1024 + pix;
        uint32_t w = 0;
        if (xb[0]    > 0.f) w |= 1u;
        if (xb[1024] > 0.f) w |= 2u;
        if (xb[2048] > 0.f) w |= 4u;
        dstx[idx] = w;
        return;
    }
    const int cumw[7] = {0, 384, 4992, 14208, 32640, 63360, 104320};
    const int woff[6] = {0, 3456, 44928, 127872, 293760, 570240};
    const int cin[6]  = {3, 344, 352, 686, 679, 1246};
    const int cout[6] = {344, 352, 686, 679, 1246, 973};
    const int winp[6] = {1, 12, 12, 24, 24, 40};

    int wn = (idx >> 5) - 8192;
    int lane = idx & 31;
    if (wn >= 104320) return;

    int l = 0;
#pragma unroll
    for (int i = 1; i < 6; ++i) if (wn >= cumw[i]) l = i;

    const float* wsrc = (l == 0) ? w0 : (l == 1) ? w1 : (l == 2) ? w2
                       : (l == 3) ? w3 : (l == 4) ? w4 : w5;
    const int Ci = cin[l], Co = cout[l], WINP = winp[l];

    int widx = wn - cumw[l];
    int q  = widx % WINP;  widx /= WINP;
    int cl = widx & 31;
    int wi = widx >> 5;
    int co = wi * 32 + cl;
    int ci = q * 32 + lane;

    const bool valid = (co < Co && ci < Ci);
    const float* src = valid ? (wsrc + ((size_t)co * Ci + ci) * 9) : wsrc;
    uint32_t* dbase = dstw + woff[l] + ((size_t)wi * 9 * 32 + cl) * WINP + q;
#pragma unroll
    for (int tap = 0; tap < 9; ++tap) {
        float v = valid ? src[tap] : 0.f;
        uint32_t bits = __ballot_sync(0xFFFFFFFFu, valid && v > 0.f);
        if (lane == 0) dbase[(size_t)tap * 32 * WINP] = bits;
    }
}

// ---------------------------------------------------------------------------
// Merged pack: FC weights ballot + per-tap weight popcounts + BN thresholds.
__global__ void pack_misc_kernel(const uint32_t* __restrict__ wpk,
                                 const float* __restrict__ fcw,
                                 const float* __restrict__ p0, const float* __restrict__ p1,
                                 const float* __restrict__ p2, const float* __restrict__ p3,
                                 const float* __restrict__ p4, const float* __restrict__ p5,
                                 int* __restrict__ pw, float2* __restrict__ th,
                                 uint32_t* __restrict__ fcpk)
{
    int idx = blockIdx.x * blockDim.x + threadIdx.x;
    if (idx < 163840) {
        int warp = idx >> 5;
        int lane = idx & 31;
        int wi = warp & 31; int r = warp >> 5;
        int s = r & 15; int o = r >> 4;
        int c = wi * 32 + lane;
        float v = (c < 973) ? fcw[(size_t)o * 15568 + c * 16 + s] : 0.f;
        uint32_t bits = __ballot_sync(0xFFFFFFFFu, v > 0.f);
        if (lane == 0) fcpk[warp] = bits;
    } else if (idx < 163840 + 41472) {
        int i1 = idx - 163840;
        const int cum9[7]  = {0, 3456, 6912, 13824, 20736, 32256, 41472};
        const int woff[6]  = {0, 3456, 44928, 127872, 293760, 570240};
        const int winp[6]  = {1, 12, 12, 24, 24, 40};
        int l = 0;
#pragma unroll
        for (int i = 1; i < 6; ++i) if (i1 >= cum9[i]) l = i;
        int t = i1 - cum9[l];
        int cl  = t & 31;  t >>= 5;
        int tap = t % 9;
        int wi  = t / 9;
        const int WINP = winp[l];
        const uint32_t* src = wpk + woff[l] + (((size_t)wi * 9 + tap) * 32 + cl) * WINP;
        int s = 0;
        for (int q = 0; q < WINP; ++q) s += __popc(src[q]);
        pw[i1] = s;
    } else if (idx < 163840 + 41472 + 4608) {
        int i2 = idx - 163840 - 41472;
        const int cum[7]  = {0, 384, 768, 1536, 2304, 3584, 4608};
        const int cout[6] = {344, 352, 686, 679, 1246, 973};
        int l = 0;
#pragma unroll
        for (int i = 1; i < 6; ++i) if (i2 >= cum[i]) l = i;
        const float* p = (l == 0) ? p0 : (l == 1) ? p1 : (l == 2) ? p2
                        : (l == 3) ? p3 : (l == 4) ? p4 : p5;
        int c = i2 - cum[l];
        int Co = cout[l];
        float2 t;
        if (c < Co) {
            float gg = p[c], bb = p[Co + c], mm = p[2 * Co + c], vv = p[3 * Co + c];
            float sc = gg * rsqrtf(vv + 1e-5f);
            t.x = sc; t.y = bb - mm * sc;
        } else {
            t.x = 0.f; t.y = -1.f;
        }
        th[i2] = t;
    }
}

// ---------------------------------------------------------------------------
// Binary conv 3x3 pad 1, branch-free all-9-taps + edge correction, CSA popc,
// fma-pipe accumulation, kx unrolled, pad words skipped (REALW).
// uint4-vectorized smem fills; thresholds staged in smem once per block.
template <int WINP, int REALW>
__global__ void __launch_bounds__(256, 4)
bconv_kernel(const uint32_t* __restrict__ in, uint8_t* __restrict__ out,
             const uint32_t* __restrict__ wpk, const int* __restrict__ pw,
             const float2* __restrict__ th,
             int H, int W, int Cin, int WOUTP, int tilesX, int one, int two)
{
    constexpr int FB = REALW / 12;        // full 12-word CSA blocks
    constexpr int L  = REALW - FB * 12;   // leftover real words (11, 10, 3, 1/0)
    constexpr int W4 = WINP / 4;          // uint4s per pixel (0 for WINP=1)

    extern __shared__ uint32_t sm[];
    uint32_t* sw  = sm;                            // 9*32*WINP
    int*      spw = (int*)(sm + 9 * 32 * WINP);    // 288
    float2*   sth = (float2*)(spw + 288);          // 32 float2 = 64 words
    uint32_t* sx  = (uint32_t*)(sth + 32);         // 100*WINP
    const int tid = threadIdx.x;
    const int wi = blockIdx.y;
    const int x0 = (blockIdx.x % tilesX) * 8;
    const int y0 = (blockIdx.x / tilesX) * 8;

    const uint32_t* wsrc = wpk + (size_t)wi * (9 * 32 * WINP);
    if (WINP == 1) {
        for (int i = tid; i < 288; i += 256) sw[i] = wsrc[i];
    } else {
        const uint4* ws4 = (const uint4*)wsrc;
        uint4* sw4 = (uint4*)sw;
        for (int i = tid; i < 9 * 32 * W4; i += 256) sw4[i] = ws4[i];
    }
    if (tid < 288) spw[tid] = pw[(size_t)wi * 288 + tid];
    { int i2 = tid + 256; if (i2 < 288) spw[i2] = pw[(size_t)wi * 288 + i2]; }
    if (tid < 32) sth[tid] = th[wi * 32 + tid];

    const int g  = tid >> 6;
    const int p  = tid & 63;
    const int py = p >> 3;
    const int px = p & 7;

    for (int it = 0; it < IMGS_PER_BLK; ++it) {
        const int n = blockIdx.z * IMGS_PER_BLK + it;
        __syncthreads();
        const uint32_t* ibase = in + (size_t)n * H * W * WINP;
        if (WINP == 1) {
            if (tid < 100) {
                const int iy = y0 + tid / 10 - 1;
                const int ix = x0 + tid % 10 - 1;
                sx[tid] = (iy >= 0 && iy < H && ix >= 0 && ix < W)
                        ? ibase[iy * W + ix] : 0u;
            }
        } else {
            for (int i = tid; i < 100 * W4; i += 256) {
                const int w4 = i % W4;
                const int pp = i / W4;
                const int iy = y0 + pp / 10 - 1;
                const int ix = x0 + pp % 10 - 1;
                uint4 v = make_uint4(0u, 0u, 0u, 0u);
                if (iy >= 0 && iy < H && ix >= 0 && ix < W)
                    v = *(const uint4*)(ibase + ((size_t)iy * W + ix) * WINP + w4 * 4);
                *(uint4*)(sx + pp * WINP + w4 * 4) = v;
            }
        }
        __syncthreads();

        int D[8];
#pragma unroll
        for (int j = 0; j < 8; ++j) D[j] = 0;

#pragma unroll 1
        for (int ky = 0; ky < 3; ++ky) {
            const uint32_t* xrow = &sx[((py + ky) * 10 + px) * WINP];
            const uint32_t* wrow = &sw[(ky * 3 * 32 + g * 8) * WINP];
#pragma unroll
            for (int kx = 0; kx < 3; ++kx) {
                const uint32_t* xp = xrow + kx * WINP;
                const uint32_t* wp = wrow + kx * 32 * WINP;
                if (WINP == 1) {
                    const uint32_t xv = xp[0];
#pragma unroll
                    for (int j = 0; j < 8; ++j)
                        madacc(D[j], __popc(xv ^ wp[j]), one);
                } else {
#pragma unroll
                    for (int t3 = 0; t3 < FB; ++t3) {
                        const uint4 x0v = *(const uint4*)(xp + t3 * 12);
                        const uint4 x1v = *(const uint4*)(xp + t3 * 12 + 4);
                        const uint4 x2v = *(const uint4*)(xp + t3 * 12 + 8);
#pragma unroll
                        for (int j = 0; j < 8; ++j) {
                            const uint32_t* wj = wp + j * WINP + t3 * 12;
                            const uint4 w0v = *(const uint4*)(wj);
                            const uint4 w1v = *(const uint4*)(wj + 4);
                            const uint4 w2v = *(const uint4*)(wj + 8);
                            uint32_t a, b, c;
                            uint32_t s0, s1, s2, s3, m0, m1, m2, m3;
                            a = x0v.x ^ w0v.x; b = x1v.x ^ w1v.x; c = x2v.x ^ w2v.x;
                            s0 = a ^ b ^ c; m0 = (a & b) | (c & (a | b));
                            a = x0v.y ^ w0v.y; b = x1v.y ^ w1v.y; c = x2v.y ^ w2v.y;
                            s1 = a ^ b ^ c; m1 = (a & b) | (c & (a | b));
                            a = x0v.z ^ w0v.z; b = x1v.z ^ w1v.z; c = x2v.z ^ w2v.z;
                            s2 = a ^ b ^ c; m2 = (a & b) | (c & (a | b));
                            a = x0v.w ^ w0v.w; b = x1v.w ^ w1v.w; c = x2v.w ^ w2v.w;
                            s3 = a ^ b ^ c; m3 = (a & b) | (c & (a | b));
                            madacc(D[j], __popc(s0), one);
                            madacc(D[j], __popc(s1), one);
                            madacc(D[j], __popc(s2), one);
                            madacc(D[j], __popc(s3), one);
                            madacc(D[j], __popc(m0), two);
                            madacc(D[j], __popc(m1), two);
                            madacc(D[j], __popc(m2), two);
                            madacc(D[j], __popc(m3), two);
                        }
                    }
                    if (L == 11) {      // cols 0-2 CSA, col 3 plain pair (skip pad)
                        const uint32_t* xq = xp + FB * 12;
                        const uint4 x0v = *(const uint4*)(xq);
                        const uint4 x1v = *(const uint4*)(xq + 4);
                        const uint4 x2v = *(const uint4*)(xq + 8);
#pragma unroll
                        for (int j = 0; j < 8; ++j) {
                            const uint32_t* wj = wp + j * WINP + FB * 12;
                            const uint4 w0v = *(const uint4*)(wj);
                            const uint4 w1v = *(const uint4*)(wj + 4);
                            const uint4 w2v = *(const uint4*)(wj + 8);
                            uint32_t a, b, c, s0, s1, s2, m0, m1, m2;
                            a = x0v.x ^ w0v.x; b = x1v.x ^ w1v.x; c = x2v.x ^ w2v.x;
                            s0 = a ^ b ^ c; m0 = (a & b) | (c & (a | b));
                            a = x0v.y ^ w0v.y; b = x1v.y ^ w1v.y; c = x2v.y ^ w2v.y;
                            s1 = a ^ b ^ c; m1 = (a & b) | (c & (a | b));
                            a = x0v.z ^ w0v.z; b = x1v.z ^ w1v.z; c = x2v.z ^ w2v.z;
                            s2 = a ^ b ^ c; m2 = (a & b) | (c & (a | b));
                            madacc(D[j], __popc(s0), one);
                            madacc(D[j], __popc(s1), one);
                            madacc(D[j], __popc(s2), one);
                            madacc(D[j], __popc(m0), two);
                            madacc(D[j], __popc(m1), two);
                            madacc(D[j], __popc(m2), two);
                            madacc(D[j], __popc(x0v.w ^ w0v.w), one);
                            madacc(D[j], __popc(x1v.w ^ w1v.w), one);
                        }
                    }
                    if (L == 10) {      // cols 0,1 CSA; cols 2,3 plain pairs
                        const uint32_t* xq = xp + FB * 12;
                        const uint4 x0v = *(const uint4*)(xq);
                        const uint4 x1v = *(const uint4*)(xq + 4);
                        const uint4 x2v = *(const uint4*)(xq + 8);
#pragma unroll
                        for (int j = 0; j < 8; ++j) {
                            const uint32_t* wj = wp + j * WINP + FB * 12;
                            const uint4 w0v = *(const uint4*)(wj);
                            const uint4 w1v = *(const uint4*)(wj + 4);
                            const uint4 w2v = *(const uint4*)(wj + 8);
                            uint32_t a, b, c, s0, s1, m0, m1;
                            a = x0v.x ^ w0v.x; b = x1v.x ^ w1v.x; c = x2v.x ^ w2v.x;
                            s0 = a ^ b ^ c; m0 = (a & b) | (c & (a | b));
                            a = x0v.y ^ w0v.y; b = x1v.y ^ w1v.y; c = x2v.y ^ w2v.y;
                            s1 = a ^ b ^ c; m1 = (a & b) | (c & (a | b));
                            madacc(D[j], __popc(s0), one);
                            madacc(D[j], __popc(s1), one);
                            madacc(D[j], __popc(m0), two);
                            madacc(D[j], __popc(m1), two);
                            madacc(D[j], __popc(x0v.z ^ w0v.z), one);
                            madacc(D[j], __popc(x1v.z ^ w1v.z), one);
                            madacc(D[j], __popc(x0v.w ^ w0v.w), one);
                            madacc(D[j], __popc(x1v.w ^ w1v.w), one);
                        }
                    }
                    if (L == 3) {       // three plain words (skip pad)
                        const uint4 xv = *(const uint4*)(xp + FB * 12);
#pragma unroll
                        for (int j = 0; j < 8; ++j) {
                            const uint4 wv = *(const uint4*)(wp + j * WINP + FB * 12);
                            madacc(D[j], __popc(xv.x ^ wv.x), one);
                            madacc(D[j], __popc(xv.y ^ wv.y), one);
                            madacc(D[j], __popc(xv.z ^ wv.z), one);
                        }
                    }
                }
            }
        }

        const int y = y0 + py, x = x0 + px;
        const bool eT = (y == 0), eB = (y == H - 1), eL = (x == 0), eR = (x == W - 1);
        const bool edge = eT | eB | eL | eR;
        const int nvCin = (3 - (int)eT - (int)eB) * (3 - (int)eL - (int)eR) * Cin;
        unsigned bytev = 0u;
#pragma unroll
        for (int j = 0; j < 8; ++j) {
            int corr = 0;
            if (edge) {
#pragma unroll
                for (int ky = 0; ky < 3; ++ky)
#pragma unroll
                    for (int kx = 0; kx < 3; ++kx) {
                        const bool inv = (eT && ky == 0) || (eB && ky == 2)
                                      || (eL && kx == 0) || (eR && kx == 2);
                        if (inv) corr += spw[(ky * 3 + kx) * 32 + g * 8 + j];
                    }
            }
            const int idot = nvCin - 2 * D[j] + 2 * corr;
            const float2 t = sth[g * 8 + j];
            if (fmaf((float)idot, t.x, t.y) > 0.0f) bytev |= 1u << j;
        }
        out[(((size_t)n * H * W + (size_t)y * W + x) * WOUTP + wi) * 4 + g]
            = (uint8_t)bytev;
    }
}

// Maxpool 2x2 on packed bits == bitwise OR. Words w >= realW are written as 0.
__global__ void pool_kernel(const uint32_t* __restrict__ in, uint32_t* __restrict__ out,
                            int Ho, int Wo, int WORDS, int realW, int total)
{
    int idx = blockIdx.x * blockDim.x + threadIdx.x;
    if (idx >= total) return;
    int w = idx % WORDS; int r = idx / WORDS;
    int xo = r % Wo; r /= Wo;
    int yo = r % Ho; int n = r / Ho;
    if (w >= realW) { out[idx] = 0u; return; }
    const int Wi = Wo * 2;
    size_t base = (((size_t)n * (Ho * 2) + yo * 2) * Wi + xo * 2) * WORDS + w;
    size_t rs = (size_t)Wi * WORDS;
    out[idx] = in[base] | in[base + WORDS] | in[base + rs] | in[base + rs + WORDS];
}

// Zero pad cout-words of a conv output the conv no longer computes.
__global__ void zero_pads_kernel(uint32_t* __restrict__ out, int WORDS, int w0,
                                 int nw, int total)
{
    int idx = blockIdx.x * blockDim.x + threadIdx.x;
    if (idx >= total) return;
    int p = idx / nw, k = idx - p * nw;
    out[(size_t)p * WORDS + w0 + k] = 0u;
}

// Binary FC: out[n][o] = 15568 - 2*popc(x ^ w) + fcb[o]
__global__ void fc_kernel(const uint32_t* __restrict__ xb, const uint32_t* __restrict__ wb,
                          const float* __restrict__ fcb, float* __restrict__ out)
{
    int t = blockIdx.x * blockDim.x + threadIdx.x;
    if (t >= NIMG * 10) return;
    int n = t / 10, o = t - n * 10;
    const uint4* xa = (const uint4*)(xb + (size_t)n * 512);
    const uint4* wa = (const uint4*)(wb + (size_t)o * 512);
    int D = 0;
#pragma unroll 8
    for (int i = 0; i < 128; ++i) {
        uint4 a = xa[i], b = wa[i];
        D += __popc(a.x ^ b.x) + __popc(a.y ^ b.y) + __popc(a.z ^ b.z) + __popc(a.w ^ b.w);
    }
    out[t] = (float)(15568 - 2 * D) + fcb[o];
}

// ---------------------------------------------------------------------------
extern "C" void kernel_launch(void* const* d_in, const int* in_sizes, int n_in,
                              void* d_out, int out_size)
{
    static const int s_cin[6]   = {3, 344, 352, 686, 679, 1246};
    static const int s_H[6]     = {32, 32, 16, 16, 8, 8};
    static const int s_winp[6]  = {1, 12, 12, 24, 24, 40};
    static const int s_woutp[6] = {12, 12, 24, 24, 40, 32};   // storage strides
    static const int s_gy[6]    = {12, 11, 22, 22, 39, 31};   // computed groups
    static const size_t s_woff[6] = {0, 3456, 44928, 127872, 293760, 570240};
    static const size_t s_toff[6] = {0, 384, 768, 1536, 2304, 3584};

    const long long szw[6] = {344LL*3*9, 352LL*344*9, 686LL*352*9,
                              679LL*686*9, 1246LL*679*9, 973LL*1246*9};
    const long long szp[6] = {4LL*344, 4LL*352, 4LL*686, 4LL*679, 4LL*1246, 4LL*973};
    auto find = [&](long long s) -> const void* {
        for (int i = 0; i < n_in; ++i)
            if ((long long)in_sizes[i] == s) return d_in[i];
        return (const void*)0;
    };
    const float* x   = (const float*)find(256LL * 3 * 32 * 32);
    const float* fcw = (const float*)find(10LL * 15568);
    const float* fcb = (const float*)find(10);
    const float* w[6]; const float* p[6];
    for (int i = 0; i < 6; ++i) {
        w[i] = (const float*)find(szw[i]);
        p[i] = (const float*)find(szp[i]);
    }
    if (!x || !fcw || !fcb) return;

    void *pA, *pB, *pW, *pPW, *pT, *pF;
    cudaGetSymbolAddress(&pA, g_bufA);
    cudaGetSymbolAddress(&pB, g_bufB);
    cudaGetSymbolAddress(&pW, g_wpk);
    cudaGetSymbolAddress(&pPW, g_wpw);
    cudaGetSymbolAddress(&pT, g_th);
    cudaGetSymbolAddress(&pF, g_fcpk);
    uint32_t* bufA = (uint32_t*)pA;
    uint32_t* bufB = (uint32_t*)pB;
    uint32_t* wpk  = (uint32_t*)pW;
    int*      wpw  = (int*)pPW;
    float2*   th   = (float2*)pT;
    uint32_t* fcpk = (uint32_t*)pF;

    auto smemFor = [](int winp) { return (size_t)(9 * 32 * winp + 288 + 64 + 100 * winp) * 4; };
    cudaFuncSetAttribute(bconv_kernel<40,39>, cudaFuncAttributeMaxDynamicSharedMemorySize, (int)smemFor(40));
    cudaFuncSetAttribute(bconv_kernel<24,22>, cudaFuncAttributeMaxDynamicSharedMemorySize, (int)smemFor(24));

    // --- pack phase: 2 launches ---
    {
        int tot = NIMG * 1024 + 104320 * 32;
        pack_xw_kernel<<<(tot + 255) / 256, 256>>>(x, w[0], w[1], w[2], w[3], w[4], w[5],
                                                   bufA, wpk);
    }
    {
        int tot = 163840 + 41472 + 4608;
        pack_misc_kernel<<<(tot + 255) / 256, 256>>>(wpk, fcw, p[0], p[1], p[2], p[3], p[4], p[5],
                                                     wpw, th, fcpk);
    }

    // --- conv stack ---
    auto conv = [&](int l, const uint32_t* src, uint32_t* dst) {
        int H = s_H[l], W = H;
        int WINP = s_winp[l], WOUTP = s_woutp[l], Cin = s_cin[l];
        int tilesX = W / 8;
        dim3 grid((unsigned)((H / 8) * tilesX), (unsigned)s_gy[l],
                  (unsigned)(NIMG / IMGS_PER_BLK));
        size_t smem = smemFor(WINP);
        uint8_t* ob = (uint8_t*)dst;
        const uint32_t* wb = wpk + s_woff[l];
        const int* pwb = wpw + s_toff[l] * 9;
        const float2* tb = th + s_toff[l];
        switch (l) {
            case 0:           bconv_kernel<1,1>  <<<grid, 256, smem>>>(src, ob, wb, pwb, tb, H, W, Cin, WOUTP, tilesX, 1, 2); break;
            case 1: case 2:   bconv_kernel<12,11><<<grid, 256, smem>>>(src, ob, wb, pwb, tb, H, W, Cin, WOUTP, tilesX, 1, 2); break;
            case 3: case 4:   bconv_kernel<24,22><<<grid, 256, smem>>>(src, ob, wb, pwb, tb, H, W, Cin, WOUTP, tilesX, 1, 2); break;
            case 5:           bconv_kernel<40,39><<<grid, 256, smem>>>(src, ob, wb, pwb, tb, H, W, Cin, WOUTP, tilesX, 1, 2); break;
        }
    };

    conv(0, bufA, bufB);                                    // B: [32,32,12]
    conv(1, bufB, bufA);                                    // A: conv-space [32,32,12], groups 0..10
    {   int tot = NIMG * 16 * 16 * 12;
        pool_kernel<<<(tot + 255) / 256, 256>>>(bufA, bufB, 16, 16, 12, 11, tot); }  // B: [16,16,12]
    {   int tot = NIMG * 16 * 16 * 2;   // zero l2 output pad words 22,23 of bufA
        zero_pads_kernel<<<(tot + 255) / 256, 256>>>(bufA, 24, 22, 2, tot); }
    conv(2, bufB, bufA);                                    // A: [16,16,24], groups 0..21
    conv(3, bufA, bufB);                                    // B: conv-space [16,16,24], groups 0..21
    {   int tot = NIMG * 8 * 8 * 24;
        pool_kernel<<<(tot + 255) / 256, 256>>>(bufB, bufA, 8, 8, 24, 22, tot); }    // A: [8,8,24]
    {   int tot = NIMG * 8 * 8;          // zero l4 output pad word 39 of bufB
        zero_pads_kernel<<<(tot + 255) / 256, 256>>>(bufB, 40, 39, 1, tot); }
    conv(4, bufA, bufB);                                    // B: [8,8,40], groups 0..38
    conv(5, bufB, bufA);                                    // A: conv-space [8,8,32], groups 0..30
    {   int tot = NIMG * 4 * 4 * 32;
        pool_kernel<<<(tot + 255) / 256, 256>>>(bufA, bufB, 4, 4, 32, 31, tot); }    // B: [4,4,32]

    // --- FC ---
    fc_kernel<<<10, 256>>>(bufB, fcpk, fcb, (float*)d_out);
}